// round 9
// baseline (speedup 1.0000x reference)
#include <cuda_runtime.h>
#include <math.h>
#include <stdint.h>

// Problem constants
#define BB 4
#define TT 2048
#define INF_ 64
#define DD 512
#define HH 8
#define DH 64
#define FF_ 2048
#define LL 4
#define LAT 128
#define PAST 40
#define FUT 120
#define ROWS (BB*TT)          // 8192
#define EPS 1e-5f

// ---------------- scratch (device globals; no allocation allowed) ----------
__device__ float g_x   [ROWS * DD];
__device__ float g_qkv [ROWS * 3 * DD];
__device__ float g_ctx [ROWS * DD];
__device__ float g_tmp [ROWS * DD];
__device__ float g_ff  [ROWS * FF_];
__device__ float g_pool[BB * DD];
__device__ float g_pp  [BB * 32 * DD];
__device__ float g_h   [BB * 2 * LAT];

// ---------------- helpers ---------------------------------------------------
__device__ __forceinline__ float f2tf(float x) {
    uint32_t u; asm("cvt.rna.tf32.f32 %0, %1;" : "=r"(u) : "f"(x));
    return __uint_as_float(u);
}
__device__ __forceinline__ uint32_t f2tfu(float x) {
    uint32_t u; asm("cvt.rna.tf32.f32 %0, %1;" : "=r"(u) : "f"(x));
    return u;
}
__device__ __forceinline__ uint32_t sptr(const void* p) {
    return (uint32_t)__cvta_generic_to_shared(p);
}
__device__ __forceinline__ void cpa16(uint32_t dst, const void* src) {
    asm volatile("cp.async.cg.shared.global [%0], [%1], 16;\n" :: "r"(dst), "l"(src));
}
#define CP_COMMIT() asm volatile("cp.async.commit_group;\n")
#define CP_WAIT(n)  asm volatile("cp.async.wait_group %0;\n" :: "n"(n))

#define MMA_TF32(d0,d1,d2,d3,a0,a1,a2,a3,b0,b1)                              \
    asm volatile("mma.sync.aligned.m16n8k8.row.col.f32.tf32.tf32.f32 "       \
        "{%0,%1,%2,%3},{%4,%5,%6,%7},{%8,%9},{%0,%1,%2,%3};"                 \
        : "+f"(d0),"+f"(d1),"+f"(d2),"+f"(d3)                                \
        : "r"(a0),"r"(a1),"r"(a2),"r"(a3),"r"(b0),"r"(b1))

// ---------------- TF32 GEMM, fragment-contiguous smem layout ----------------
// C[M,N] = A[M,K] @ B[K,N] + bias. BM=BN=128, BK=16, 8 warps (64x32 tiles).
// Smem stores pre-converted tf32 values in per-fragment order:
//   As[buf][kk][mtile(8)][lane(32)][4]  -> one LDS.128 per A-fragment
//   Bs[buf][kk][ntile(16)][lane(32)][2] -> one LDS.64  per B-fragment
// EPI: 0 = +bias ; 1 = +bias, relu ; 2 = +bias + pos_enc[row%T]
template <int EPI>
__global__ __launch_bounds__(256)
void gemm_frag(const float* __restrict__ A, const float* __restrict__ B,
               const float* __restrict__ bias, const float* __restrict__ extra,
               float* __restrict__ C, int M, int N, int K)
{
    __shared__ float As[2][2][8][32][4];    // 16 KB
    __shared__ float Bs[2][2][16][32][2];   // 16 KB

    const int tid  = threadIdx.x;
    const int wid  = tid >> 5, lane = tid & 31;
    const int brow = blockIdx.y * 128, bcol = blockIdx.x * 128;

    // A loader: thread t owns row arow = t>>1, k-half khalf = t&1 (8 floats)
    const int arow  = tid >> 1, khalf = tid & 1;
    const int a_mt  = arow >> 4;
    const int a_g   = arow & 7;
    const int a_h   = (arow >> 3) & 1;
    // B loader: thread t owns k-row brw = t>>4, 8 cols from ncol0 = (t&15)*8
    const int brw   = tid >> 4;
    const int b_kk  = brw >> 3;
    const int b_c   = brw & 3;
    const int b_j   = (brw >> 2) & 1;
    const int b_nt  = tid & 15;

    const float* Ag = A + (size_t)(brow + arow) * K + khalf * 8;
    const float* Bg = B + bcol + b_nt * 8;

    float acc[4][4][4];
#pragma unroll
    for (int i = 0; i < 4; i++)
#pragma unroll
        for (int j = 0; j < 4; j++)
#pragma unroll
            for (int r = 0; r < 4; r++) acc[i][j][r] = 0.f;

    const int nk = K >> 4;   // BK = 16

    float4 pa0, pa1, pb0, pb1;
    pa0 = *(const float4*)(Ag);
    pa1 = *(const float4*)(Ag + 4);
    pb0 = *(const float4*)(Bg + (size_t)brw * N);
    pb1 = *(const float4*)(Bg + (size_t)brw * N + 4);

    // store stage into frag layout (pre-converted tf32)
    auto store_stage = [&](int buf, float4 a0, float4 a1, float4 b0, float4 b1) {
        float* ap = &As[buf][khalf][a_mt][a_g * 4][a_h];
        // value i (k = i): c = i&3, j = i>>2 -> As[..][g*4+c][h+2*j]
        ap[0 * 4 + 0] = f2tf(a0.x);          // c0 j0
        ap[1 * 4 + 0] = f2tf(a0.y);          // c1 j0
        ap[2 * 4 + 0] = f2tf(a0.z);
        ap[3 * 4 + 0] = f2tf(a0.w);
        ap[0 * 4 + 2] = f2tf(a1.x);          // c0 j1
        ap[1 * 4 + 2] = f2tf(a1.y);
        ap[2 * 4 + 2] = f2tf(a1.z);
        ap[3 * 4 + 2] = f2tf(a1.w);
        float* bp = &Bs[buf][b_kk][b_nt][b_c][b_j];
        // value g (col): Bs[..][g*4+c][j]
        bp[0 * 8 + 0] = f2tf(b0.x);          // g0
        bp[1 * 8 + 0] = f2tf(b0.y);
        bp[2 * 8 + 0] = f2tf(b0.z);
        bp[3 * 8 + 0] = f2tf(b0.w);
        bp[4 * 8 + 0] = f2tf(b1.x);
        bp[5 * 8 + 0] = f2tf(b1.y);
        bp[6 * 8 + 0] = f2tf(b1.z);
        bp[7 * 8 + 0] = f2tf(b1.w);
    };

    store_stage(0, pa0, pa1, pb0, pb1);
    __syncthreads();

    const int mtb = (wid >> 2) * 4;   // warp's first mtile
    const int ntb = (wid & 3) * 4;    // warp's first ntile

    for (int s = 0; s < nk; s++) {
        if (s + 1 < nk) {
            const float* Agn = Ag + (s + 1) * 16;
            const float* Bgn = Bg + (size_t)((s + 1) * 16 + brw) * N;
            pa0 = *(const float4*)(Agn);
            pa1 = *(const float4*)(Agn + 4);
            pb0 = *(const float4*)(Bgn);
            pb1 = *(const float4*)(Bgn + 4);
        }

        const int buf = s & 1;
#pragma unroll
        for (int kk = 0; kk < 2; kk++) {
            uint4 af[4];
            uint2 bf[4];
#pragma unroll
            for (int mt = 0; mt < 4; mt++)
                af[mt] = *(const uint4*)&As[buf][kk][mtb + mt][lane][0];
#pragma unroll
            for (int nt = 0; nt < 4; nt++)
                bf[nt] = *(const uint2*)&Bs[buf][kk][ntb + nt][lane][0];
#pragma unroll
            for (int mt = 0; mt < 4; mt++)
#pragma unroll
                for (int nt = 0; nt < 4; nt++)
                    MMA_TF32(acc[mt][nt][0], acc[mt][nt][1], acc[mt][nt][2], acc[mt][nt][3],
                             af[mt].x, af[mt].y, af[mt].z, af[mt].w,
                             bf[nt].x, bf[nt].y);
        }

        if (s + 1 < nk) {
            store_stage(buf ^ 1, pa0, pa1, pb0, pb1);
            __syncthreads();
        }
    }

    // epilogue: frag (row g/g+8, col 2c/2c+1)
    const int g = lane >> 2, c = lane & 3;
    const int wm = (wid >> 2) * 64, wn = (wid & 3) * 32;
#pragma unroll
    for (int mt = 0; mt < 4; mt++) {
#pragma unroll
        for (int nt = 0; nt < 4; nt++) {
            const int col = bcol + wn + nt * 8 + 2 * c;
            const float b0 = bias[col], b1 = bias[col + 1];
#pragma unroll
            for (int half = 0; half < 2; half++) {
                const int row = brow + wm + mt * 16 + g + half * 8;
                float v0 = acc[mt][nt][half * 2 + 0] + b0;
                float v1 = acc[mt][nt][half * 2 + 1] + b1;
                if (EPI == 1) { v0 = fmaxf(v0, 0.f); v1 = fmaxf(v1, 0.f); }
                if (EPI == 2) {
                    const int t = row & (TT - 1);
                    v0 += extra[(size_t)t * N + col];
                    v1 += extra[(size_t)t * N + col + 1];
                }
                float2 o; o.x = v0; o.y = v1;
                *(float2*)(C + (size_t)row * N + col) = o;
            }
        }
    }
}

// ---------------- banded flash attention (round-5 proven) --------------------
#define KVP 72
#define ABUF (64 * KVP)
#define ATTN_SMEM (4 * ABUF * 4)

__global__ __launch_bounds__(256, 2)
void attn_mma(const float* __restrict__ qkv, float* __restrict__ ctx)
{
    extern __shared__ float sm[];
    float* Ks = sm;
    float* Vs = sm + 2 * ABUF;

    const int blk = blockIdx.x;
    const int qt = blk & 15;
    const int h  = (blk >> 4) & 7;
    const int b  = blk >> 7;
    const int q0 = qt * 128;

    const int tid = threadIdx.x, wid = tid >> 5, lane = tid & 31;
    const int g = lane >> 2, c = lane & 3;
    const int w0 = q0 + wid * 16;
    const int r0 = w0 + g, r1 = r0 + 8;

    uint32_t qa[8][4];
#pragma unroll
    for (int kt = 0; kt < 8; kt++) {
        const float* q_lo = qkv + (size_t)(b * TT + r0) * 1536 + h * 64 + kt * 8;
        const float* q_hi = qkv + (size_t)(b * TT + r1) * 1536 + h * 64 + kt * 8;
        qa[kt][0] = f2tfu(q_lo[c]);
        qa[kt][1] = f2tfu(q_hi[c]);
        qa[kt][2] = f2tfu(q_lo[c + 4]);
        qa[kt][3] = f2tfu(q_hi[c + 4]);
    }

    float oacc[8][4];
#pragma unroll
    for (int nt = 0; nt < 8; nt++)
#pragma unroll
        for (int e = 0; e < 4; e++) oacc[nt][e] = 0.f;

    float m0 = -INFINITY, m1 = -INFINITY, l0 = 0.f, l1 = 0.f;
    const float scale = 0.125f;

    int csv[5]; int ncs = 0;
    const int offs[5] = {-64, 0, 64, 128, 192};
#pragma unroll
    for (int i = 0; i < 5; i++) {
        const int cs = q0 + offs[i];
        if (cs >= 0 && cs < TT) csv[ncs++] = cs;
    }

    const int lrow  = (tid >> 1) & 63;
    const int isv   = tid >> 7;
    const int lhalf = tid & 1;
    const uint32_t ldst0 = sptr((isv ? Vs : Ks) + lrow * KVP + lhalf * 32);
    const size_t lsrc_off = (size_t)512 + (size_t)isv * 512 + h * 64 + lhalf * 32;

    {
        const float* src = qkv + (size_t)(b * TT + csv[0] + lrow) * 1536 + lsrc_off;
#pragma unroll
        for (int i = 0; i < 8; i++) cpa16(ldst0 + i * 16, src + i * 4);
        CP_COMMIT();
    }

    const int srcA = (lane & 28) | (c >> 1);
    const int srcB = srcA + 2;
    const bool odd = (c & 1) != 0;

    for (int ci = 0; ci < ncs; ci++) {
        CP_WAIT(0);
        __syncthreads();

        if (ci + 1 < ncs) {
            const uint32_t dst = ldst0 + ((ci + 1) & 1) * ABUF * 4;
            const float* src = qkv + (size_t)(b * TT + csv[ci + 1] + lrow) * 1536 + lsrc_off;
#pragma unroll
            for (int i = 0; i < 8; i++) cpa16(dst + i * 16, src + i * 4);
            CP_COMMIT();
        }

        const int cs = csv[ci];
        const int lo_key = max(cs, w0 - PAST);
        const int hi_key = min(cs + 63, w0 + 15 + FUT);
        if (lo_key > hi_key) continue;
        const int ntlo = (lo_key - cs) >> 3;
        const int nthi = (hi_key - cs) >> 3;

        const float* Kb = Ks + (ci & 1) * ABUF;
        const float* Vb = Vs + (ci & 1) * ABUF;

        float sacc[8][4];
#pragma unroll
        for (int nt = 0; nt < 8; nt++) {
            sacc[nt][0] = 0.f; sacc[nt][1] = 0.f;
            sacc[nt][2] = 0.f; sacc[nt][3] = 0.f;
        }
#pragma unroll
        for (int nt = 0; nt < 8; nt++) {
            if (nt < ntlo || nt > nthi) continue;
#pragma unroll
            for (int kt = 0; kt < 8; kt++) {
                const uint32_t b0 = f2tfu(Kb[(nt * 8 + g) * KVP + kt * 8 + c]);
                const uint32_t b1 = f2tfu(Kb[(nt * 8 + g) * KVP + kt * 8 + c + 4]);
                MMA_TF32(sacc[nt][0], sacc[nt][1], sacc[nt][2], sacc[nt][3],
                         qa[kt][0], qa[kt][1], qa[kt][2], qa[kt][3], b0, b1);
            }
        }

        float mx0 = -INFINITY, mx1 = -INFINITY;
#pragma unroll
        for (int nt = 0; nt < 8; nt++) {
            if (nt < ntlo || nt > nthi) continue;
            const int j0 = cs + nt * 8 + 2 * c;
            const int j1 = j0 + 1;
            float v;
            v = sacc[nt][0] * scale;
            v = (j0 >= r0 - PAST && j0 <= r0 + FUT) ? v : -INFINITY;
            sacc[nt][0] = v; mx0 = fmaxf(mx0, v);
            v = sacc[nt][1] * scale;
            v = (j1 >= r0 - PAST && j1 <= r0 + FUT) ? v : -INFINITY;
            sacc[nt][1] = v; mx0 = fmaxf(mx0, v);
            v = sacc[nt][2] * scale;
            v = (j0 >= r1 - PAST && j0 <= r1 + FUT) ? v : -INFINITY;
            sacc[nt][2] = v; mx1 = fmaxf(mx1, v);
            v = sacc[nt][3] * scale;
            v = (j1 >= r1 - PAST && j1 <= r1 + FUT) ? v : -INFINITY;
            sacc[nt][3] = v; mx1 = fmaxf(mx1, v);
        }
        mx0 = fmaxf(mx0, __shfl_xor_sync(0xffffffffu, mx0, 1));
        mx0 = fmaxf(mx0, __shfl_xor_sync(0xffffffffu, mx0, 2));
        mx1 = fmaxf(mx1, __shfl_xor_sync(0xffffffffu, mx1, 1));
        mx1 = fmaxf(mx1, __shfl_xor_sync(0xffffffffu, mx1, 2));

        const float mn0 = fmaxf(m0, mx0);
        const float mn1 = fmaxf(m1, mx1);
        const float rf0 = __expf(fmaxf(m0 - mn0, -88.f));
        const float rf1 = __expf(fmaxf(m1 - mn1, -88.f));
        m0 = mn0; m1 = mn1;

        float ps0 = 0.f, ps1 = 0.f;
#pragma unroll
        for (int nt = 0; nt < 8; nt++) {
            if (nt < ntlo || nt > nthi) continue;
            const float p00 = __expf(fmaxf(sacc[nt][0] - mn0, -88.f));
            const float p01 = __expf(fmaxf(sacc[nt][1] - mn0, -88.f));
            const float p10 = __expf(fmaxf(sacc[nt][2] - mn1, -88.f));
            const float p11 = __expf(fmaxf(sacc[nt][3] - mn1, -88.f));
            ps0 += p00 + p01;
            ps1 += p10 + p11;
            sacc[nt][0] = f2tf(p00);
            sacc[nt][1] = f2tf(p01);
            sacc[nt][2] = f2tf(p10);
            sacc[nt][3] = f2tf(p11);
        }
        ps0 += __shfl_xor_sync(0xffffffffu, ps0, 1);
        ps0 += __shfl_xor_sync(0xffffffffu, ps0, 2);
        ps1 += __shfl_xor_sync(0xffffffffu, ps1, 1);
        ps1 += __shfl_xor_sync(0xffffffffu, ps1, 2);
        l0 = l0 * rf0 + ps0;
        l1 = l1 * rf1 + ps1;

#pragma unroll
        for (int nt = 0; nt < 8; nt++) {
            oacc[nt][0] *= rf0; oacc[nt][1] *= rf0;
            oacc[nt][2] *= rf1; oacc[nt][3] *= rf1;
        }

#pragma unroll
        for (int kt = 0; kt < 8; kt++) {
            if (kt < ntlo || kt > nthi) continue;
            float v00 = __shfl_sync(0xffffffffu, sacc[kt][0], srcA);
            float v01 = __shfl_sync(0xffffffffu, sacc[kt][1], srcA);
            float v10 = __shfl_sync(0xffffffffu, sacc[kt][2], srcA);
            float v11 = __shfl_sync(0xffffffffu, sacc[kt][3], srcA);
            const uint32_t a0 = __float_as_uint(odd ? v01 : v00);
            const uint32_t a1 = __float_as_uint(odd ? v11 : v10);
            v00 = __shfl_sync(0xffffffffu, sacc[kt][0], srcB);
            v01 = __shfl_sync(0xffffffffu, sacc[kt][1], srcB);
            v10 = __shfl_sync(0xffffffffu, sacc[kt][2], srcB);
            v11 = __shfl_sync(0xffffffffu, sacc[kt][3], srcB);
            const uint32_t a2 = __float_as_uint(odd ? v01 : v00);
            const uint32_t a3 = __float_as_uint(odd ? v11 : v10);
#pragma unroll
            for (int nt = 0; nt < 8; nt++) {
                const uint32_t b0 = f2tfu(Vb[(kt * 8 + c    ) * KVP + nt * 8 + g]);
                const uint32_t b1 = f2tfu(Vb[(kt * 8 + c + 4) * KVP + nt * 8 + g]);
                MMA_TF32(oacc[nt][0], oacc[nt][1], oacc[nt][2], oacc[nt][3],
                         a0, a1, a2, a3, b0, b1);
            }
        }
    }

    const float inv0 = 1.f / l0, inv1 = 1.f / l1;
#pragma unroll
    for (int nt = 0; nt < 8; nt++) {
        const int col = h * 64 + nt * 8 + 2 * c;
        float2 w;
        w.x = oacc[nt][0] * inv0; w.y = oacc[nt][1] * inv0;
        *(float2*)(ctx + (size_t)(b * TT + r0) * DD + col) = w;
        w.x = oacc[nt][2] * inv1; w.y = oacc[nt][3] * inv1;
        *(float2*)(ctx + (size_t)(b * TT + r1) * DD + col) = w;
    }
}

// ---------------- residual add + LayerNorm ----------------------------------
__global__ __launch_bounds__(128)
void add_ln(const float* __restrict__ x, const float* __restrict__ y,
            const float* __restrict__ s, const float* __restrict__ bta,
            float* __restrict__ out)
{
    const int row = blockIdx.x;
    const int tid = threadIdx.x;
    float v[4];
    float sum = 0.f, sq = 0.f;
#pragma unroll
    for (int i = 0; i < 4; i++) {
        int c = tid + i * 128;
        float val = x[(size_t)row * DD + c] + y[(size_t)row * DD + c];
        v[i] = val;
        sum += val;
        sq  += val * val;
    }
    __shared__ float rs[8];
#pragma unroll
    for (int off = 16; off > 0; off >>= 1) {
        sum += __shfl_xor_sync(0xffffffffu, sum, off);
        sq  += __shfl_xor_sync(0xffffffffu, sq,  off);
    }
    if ((tid & 31) == 0) { rs[tid >> 5] = sum; rs[4 + (tid >> 5)] = sq; }
    __syncthreads();
    sum = rs[0] + rs[1] + rs[2] + rs[3];
    sq  = rs[4] + rs[5] + rs[6] + rs[7];
    const float mean = sum * (1.f / DD);
    const float var  = sq * (1.f / DD) - mean * mean;
    const float inv  = rsqrtf(var + EPS);
#pragma unroll
    for (int i = 0; i < 4; i++) {
        int c = tid + i * 128;
        out[(size_t)row * DD + c] = (v[i] - mean) * inv * s[c] + bta[c];
    }
}

// ---------------- mean pool (two-stage) -------------------------------------
__global__ void pool_partial(const float* __restrict__ emb, float* __restrict__ pp)
{
    const int b = blockIdx.x >> 5, ch = blockIdx.x & 31;
    const int d = threadIdx.x;
    float s = 0.f;
    const int t0 = ch * 64;
    for (int t = t0; t < t0 + 64; t++)
        s += emb[((size_t)(b * TT + t)) * DD + d];
    pp[(size_t)blockIdx.x * DD + d] = s;
}

__global__ void pool_reduce(const float* __restrict__ pp, float* __restrict__ p)
{
    const int b = blockIdx.x, d = threadIdx.x;
    float s = 0.f;
    for (int ch = 0; ch < 32; ch++)
        s += pp[(size_t)(b * 32 + ch) * DD + d];
    p[b * DD + d] = s * (1.f / TT);
}

// ---------------- tiny dense layer (heads) ----------------------------------
__global__ void small_linear(const float* __restrict__ in, const float* __restrict__ W,
                             const float* __restrict__ bias, float* __restrict__ out,
                             int K, int N, int relu)
{
    const int b = blockIdx.x, n = threadIdx.x;
    if (n >= N) return;
    float sum = bias[n];
    for (int k = 0; k < K; k++)
        sum = fmaf(in[b * K + k], W[(size_t)k * N + n], sum);
    if (relu) sum = fmaxf(sum, 0.f);
    out[b * N + n] = sum;
}

// ---------------- launch -----------------------------------------------------
extern "C" void kernel_launch(void* const* d_in, const int* in_sizes, int n_in,
                              void* d_out, int out_size)
{
    const float* feats  = (const float*)d_in[0];
    const float* projW  = (const float*)d_in[1];
    const float* projB  = (const float*)d_in[2];
    const float* posenc = (const float*)d_in[3];
    const float* qkvW   = (const float*)d_in[4];
    const float* qkvB   = (const float*)d_in[5];
    const float* outW   = (const float*)d_in[6];
    const float* outB   = (const float*)d_in[7];
    const float* ln1s   = (const float*)d_in[8];
    const float* ln1b   = (const float*)d_in[9];
    const float* ff1W   = (const float*)d_in[10];
    const float* ff1B   = (const float*)d_in[11];
    const float* ff2W   = (const float*)d_in[12];
    const float* ff2B   = (const float*)d_in[13];
    const float* ln2s   = (const float*)d_in[14];
    const float* ln2b   = (const float*)d_in[15];
    const float* mu1W   = (const float*)d_in[16];
    const float* mu1B   = (const float*)d_in[17];
    const float* mu2W   = (const float*)d_in[18];
    const float* mu2B   = (const float*)d_in[19];
    const float* lv1W   = (const float*)d_in[20];
    const float* lv1B   = (const float*)d_in[21];
    const float* lv2W   = (const float*)d_in[22];
    const float* lv2B   = (const float*)d_in[23];

    float *px, *pqkv, *pctx, *ptmp, *pff, *ppool, *ppp, *ph;
    cudaGetSymbolAddress((void**)&px,    g_x);
    cudaGetSymbolAddress((void**)&pqkv,  g_qkv);
    cudaGetSymbolAddress((void**)&pctx,  g_ctx);
    cudaGetSymbolAddress((void**)&ptmp,  g_tmp);
    cudaGetSymbolAddress((void**)&pff,   g_ff);
    cudaGetSymbolAddress((void**)&ppool, g_pool);
    cudaGetSymbolAddress((void**)&ppp,   g_pp);
    cudaGetSymbolAddress((void**)&ph,    g_h);

    cudaFuncSetAttribute(attn_mma, cudaFuncAttributeMaxDynamicSharedMemorySize, ATTN_SMEM);

    float* emb = (float*)d_out;
    float* mu  = emb + (size_t)ROWS * DD;
    float* lv  = mu + BB * LAT;

    // x = feats @ projW + projB + posenc
    {
        dim3 grid(DD / 128, ROWS / 128);
        gemm_frag<2><<<grid, 256>>>(feats, projW, projB, posenc, px, ROWS, DD, INF_);
    }

    for (int l = 0; l < LL; l++) {
        {
            dim3 grid((3 * DD) / 128, ROWS / 128);
            gemm_frag<0><<<grid, 256>>>(px, qkvW + (size_t)l * DD * 3 * DD,
                                        qkvB + l * 3 * DD, nullptr, pqkv,
                                        ROWS, 3 * DD, DD);
        }
        attn_mma<<<BB * HH * 16, 256, ATTN_SMEM>>>(pqkv, pctx);
        {
            dim3 grid(DD / 128, ROWS / 128);
            gemm_frag<0><<<grid, 256>>>(pctx, outW + (size_t)l * DD * DD,
                                        outB + l * DD, nullptr, ptmp, ROWS, DD, DD);
        }
        add_ln<<<ROWS, 128>>>(px, ptmp, ln1s + l * DD, ln1b + l * DD, px);
        {
            dim3 grid(FF_ / 128, ROWS / 128);
            gemm_frag<1><<<grid, 256>>>(px, ff1W + (size_t)l * DD * FF_,
                                        ff1B + l * FF_, nullptr, pff, ROWS, FF_, DD);
        }
        {
            dim3 grid(DD / 128, ROWS / 128);
            gemm_frag<0><<<grid, 256>>>(pff, ff2W + (size_t)l * FF_ * DD,
                                        ff2B + l * DD, nullptr, ptmp, ROWS, DD, FF_);
        }
        float* dst = (l == LL - 1) ? emb : px;
        add_ln<<<ROWS, 128>>>(px, ptmp, ln2s + l * DD, ln2b + l * DD, dst);
    }

    pool_partial<<<BB * 32, DD>>>(emb, ppp);
    pool_reduce<<<BB, DD>>>(ppp, ppool);
    small_linear<<<BB, 2 * LAT>>>(ppool, mu1W, mu1B, ph, DD, 2 * LAT, 1);
    small_linear<<<BB, LAT>>>(ph, mu2W, mu2B, mu, 2 * LAT, LAT, 0);
    small_linear<<<BB, 2 * LAT>>>(ppool, lv1W, lv1B, ph, DD, 2 * LAT, 1);
    small_linear<<<BB, LAT>>>(ph, lv2W, lv2B, lv, 2 * LAT, LAT, 0);
}

// round 10
// speedup vs baseline: 1.9741x; 1.9741x over previous
#include <cuda_runtime.h>
#include <cuda_fp16.h>
#include <math.h>
#include <stdint.h>

// Problem constants
#define BB 4
#define TT 2048
#define INF_ 64
#define DD 512
#define HH 8
#define DH 64
#define FF_ 2048
#define LL 4
#define LAT 128
#define PAST 40
#define FUT 120
#define ROWS (BB*TT)          // 8192
#define EPS 1e-5f

// ---------------- scratch (device globals; no allocation allowed) ----------
__device__ float g_x   [ROWS * DD];
__device__ float g_qkv [ROWS * 3 * DD];
__device__ float g_ctx [ROWS * DD];
__device__ float g_tmp [ROWS * DD];
__device__ float g_ff  [ROWS * FF_];
__device__ float g_pool[BB * DD];
__device__ float g_pp  [BB * 32 * DD];
__device__ float g_h   [BB * 2 * LAT];

// ---------------- helpers ---------------------------------------------------
__device__ __forceinline__ float f2tf(float x) {
    uint32_t u; asm("cvt.rna.tf32.f32 %0, %1;" : "=r"(u) : "f"(x));
    return __uint_as_float(u);
}
__device__ __forceinline__ uint32_t f2tfu(float x) {
    uint32_t u; asm("cvt.rna.tf32.f32 %0, %1;" : "=r"(u) : "f"(x));
    return u;
}
__device__ __forceinline__ uint32_t pack_h2(float lo, float hi) {
    __half2 h = __floats2half2_rn(lo, hi);
    return *reinterpret_cast<uint32_t*>(&h);
}
__device__ __forceinline__ uint32_t sptr(const void* p) {
    return (uint32_t)__cvta_generic_to_shared(p);
}
__device__ __forceinline__ void cpa16(uint32_t dst, const void* src) {
    asm volatile("cp.async.cg.shared.global [%0], [%1], 16;\n" :: "r"(dst), "l"(src));
}
#define CP_COMMIT() asm volatile("cp.async.commit_group;\n")
#define CP_WAIT(n)  asm volatile("cp.async.wait_group %0;\n" :: "n"(n))

#define MMA_TF32(d0,d1,d2,d3,a0,a1,a2,a3,b0,b1)                              \
    asm volatile("mma.sync.aligned.m16n8k8.row.col.f32.tf32.tf32.f32 "       \
        "{%0,%1,%2,%3},{%4,%5,%6,%7},{%8,%9},{%0,%1,%2,%3};"                 \
        : "+f"(d0),"+f"(d1),"+f"(d2),"+f"(d3)                                \
        : "r"(a0),"r"(a1),"r"(a2),"r"(a3),"r"(b0),"r"(b1))

#define MMA_F16(d0,d1,d2,d3,a0,a1,a2,a3,b0,b1)                               \
    asm volatile("mma.sync.aligned.m16n8k16.row.col.f32.f16.f16.f32 "        \
        "{%0,%1,%2,%3},{%4,%5,%6,%7},{%8,%9},{%0,%1,%2,%3};"                 \
        : "+f"(d0),"+f"(d1),"+f"(d2),"+f"(d3)                                \
        : "r"(a0),"r"(a1),"r"(a2),"r"(a3),"r"(b0),"r"(b1))

// ---------------- FP16 tensor-core GEMM (m16n8k16) --------------------------
// C[M,N] = A[M,K] @ B[K,N] + bias. BM=BN=128, BK=32, 8 warps (64x32 tiles).
// Smem holds half2-packed operands (uint32 = 2 consecutive k-halves):
//   As[2][128][20]  : A row-major, 16 k-pairs + 4 pad (frag banks 20g+c distinct)
//   Bs[2][16][136]  : k-pair-major, n contiguous (frag banks 8c+g distinct;
//                     stores are contiguous uint4)
// EPI: 0 = +bias ; 1 = +bias, relu ; 2 = +bias + pos_enc[row%T]
#define AP2 20
#define BP2 136

template <int EPI>
__global__ __launch_bounds__(256)
void gemm_f16(const float* __restrict__ A, const float* __restrict__ B,
              const float* __restrict__ bias, const float* __restrict__ extra,
              float* __restrict__ C, int M, int N, int K)
{
    __shared__ uint32_t As[2][128][AP2];   // 20 KB
    __shared__ uint32_t Bs[2][16][BP2];    // 17 KB

    const int tid  = threadIdx.x;
    const int wid  = tid >> 5, lane = tid & 31;
    const int g    = lane >> 2, c = lane & 3;
    const int wm   = (wid >> 2) * 64;
    const int wn   = (wid & 3) * 32;
    const int brow = blockIdx.y * 128, bcol = blockIdx.x * 128;

    // A loader: thread t owns row t>>1, k-half kh = t&1 (16 floats)
    const int arow = tid >> 1, akh = tid & 1;
    // B loader: thread t owns k-pair r = t>>4 (rows 2r, 2r+1), n0 = (t&15)*8
    const int br = tid >> 4, bn0 = (tid & 15) * 8;

    const float* Ag = A + (size_t)(brow + arow) * K + akh * 16;
    const float* Bg = B + bcol + bn0;

    float acc[4][4][4];
#pragma unroll
    for (int i = 0; i < 4; i++)
#pragma unroll
        for (int j = 0; j < 4; j++)
#pragma unroll
            for (int r = 0; r < 4; r++) acc[i][j][r] = 0.f;

    const int nk = K >> 5;   // BK = 32

    float4 pa[4], pb[4];
    {
        const float* p = Ag;
        pa[0] = *(const float4*)(p);
        pa[1] = *(const float4*)(p + 4);
        pa[2] = *(const float4*)(p + 8);
        pa[3] = *(const float4*)(p + 12);
        const float* q0 = Bg + (size_t)(2 * br) * N;
        const float* q1 = q0 + N;
        pb[0] = *(const float4*)(q0);
        pb[1] = *(const float4*)(q0 + 4);
        pb[2] = *(const float4*)(q1);
        pb[3] = *(const float4*)(q1 + 4);
    }

    auto store_stage = [&](int buf) {
        const float* af = (const float*)pa;   // 16 consecutive k floats
        uint4 w0, w1;
        w0.x = pack_h2(af[0],  af[1]);
        w0.y = pack_h2(af[2],  af[3]);
        w0.z = pack_h2(af[4],  af[5]);
        w0.w = pack_h2(af[6],  af[7]);
        w1.x = pack_h2(af[8],  af[9]);
        w1.y = pack_h2(af[10], af[11]);
        w1.z = pack_h2(af[12], af[13]);
        w1.w = pack_h2(af[14], af[15]);
        *(uint4*)&As[buf][arow][akh * 8]     = w0;
        *(uint4*)&As[buf][arow][akh * 8 + 4] = w1;

        const float* b0f = (const float*)&pb[0];  // k row 2r, 8 n's
        const float* b1f = (const float*)&pb[2];  // k row 2r+1
        uint4 v0, v1;
        v0.x = pack_h2(b0f[0], b1f[0]);
        v0.y = pack_h2(b0f[1], b1f[1]);
        v0.z = pack_h2(b0f[2], b1f[2]);
        v0.w = pack_h2(b0f[3], b1f[3]);
        v1.x = pack_h2(b0f[4], b1f[4]);
        v1.y = pack_h2(b0f[5], b1f[5]);
        v1.z = pack_h2(b0f[6], b1f[6]);
        v1.w = pack_h2(b0f[7], b1f[7]);
        *(uint4*)&Bs[buf][br][bn0]     = v0;
        *(uint4*)&Bs[buf][br][bn0 + 4] = v1;
    };

    store_stage(0);
    __syncthreads();

    for (int s = 0; s < nk; s++) {
        if (s + 1 < nk) {
            const float* p = Ag + (s + 1) * 32;
            pa[0] = *(const float4*)(p);
            pa[1] = *(const float4*)(p + 4);
            pa[2] = *(const float4*)(p + 8);
            pa[3] = *(const float4*)(p + 12);
            const float* q0 = Bg + (size_t)((s + 1) * 32 + 2 * br) * N;
            const float* q1 = q0 + N;
            pb[0] = *(const float4*)(q0);
            pb[1] = *(const float4*)(q0 + 4);
            pb[2] = *(const float4*)(q1);
            pb[3] = *(const float4*)(q1 + 4);
        }

        const int buf = s & 1;
#pragma unroll
        for (int kk = 0; kk < 2; kk++) {
            uint32_t af[4][4];
#pragma unroll
            for (int mt = 0; mt < 4; mt++) {
                const int m0 = wm + mt * 16 + g;
                af[mt][0] = As[buf][m0    ][kk * 8 + c];
                af[mt][1] = As[buf][m0 + 8][kk * 8 + c];
                af[mt][2] = As[buf][m0    ][kk * 8 + c + 4];
                af[mt][3] = As[buf][m0 + 8][kk * 8 + c + 4];
            }
            uint32_t bf[4][2];
#pragma unroll
            for (int nt = 0; nt < 4; nt++) {
                const int n0 = wn + nt * 8 + g;
                bf[nt][0] = Bs[buf][kk * 8 + c    ][n0];
                bf[nt][1] = Bs[buf][kk * 8 + c + 4][n0];
            }
#pragma unroll
            for (int mt = 0; mt < 4; mt++)
#pragma unroll
                for (int nt = 0; nt < 4; nt++)
                    MMA_F16(acc[mt][nt][0], acc[mt][nt][1], acc[mt][nt][2], acc[mt][nt][3],
                            af[mt][0], af[mt][1], af[mt][2], af[mt][3],
                            bf[nt][0], bf[nt][1]);
        }

        if (s + 1 < nk) {
            store_stage(buf ^ 1);
            __syncthreads();
        }
    }

    // epilogue: frag (row g/g+8, col 2c/2c+1)
#pragma unroll
    for (int mt = 0; mt < 4; mt++) {
#pragma unroll
        for (int nt = 0; nt < 4; nt++) {
            const int col = bcol + wn + nt * 8 + 2 * c;
            const float b0 = bias[col], b1 = bias[col + 1];
#pragma unroll
            for (int half = 0; half < 2; half++) {
                const int row = brow + wm + mt * 16 + g + half * 8;
                float v0 = acc[mt][nt][half * 2 + 0] + b0;
                float v1 = acc[mt][nt][half * 2 + 1] + b1;
                if (EPI == 1) { v0 = fmaxf(v0, 0.f); v1 = fmaxf(v1, 0.f); }
                if (EPI == 2) {
                    const int t = row & (TT - 1);
                    v0 += extra[(size_t)t * N + col];
                    v1 += extra[(size_t)t * N + col + 1];
                }
                float2 o; o.x = v0; o.y = v1;
                *(float2*)(C + (size_t)row * N + col) = o;
            }
        }
    }
}

// ---------------- banded flash attention (round-5 proven) --------------------
#define KVP 72
#define ABUF (64 * KVP)
#define ATTN_SMEM (4 * ABUF * 4)

__global__ __launch_bounds__(256, 2)
void attn_mma(const float* __restrict__ qkv, float* __restrict__ ctx)
{
    extern __shared__ float sm[];
    float* Ks = sm;
    float* Vs = sm + 2 * ABUF;

    const int blk = blockIdx.x;
    const int qt = blk & 15;
    const int h  = (blk >> 4) & 7;
    const int b  = blk >> 7;
    const int q0 = qt * 128;

    const int tid = threadIdx.x, wid = tid >> 5, lane = tid & 31;
    const int g = lane >> 2, c = lane & 3;
    const int w0 = q0 + wid * 16;
    const int r0 = w0 + g, r1 = r0 + 8;

    uint32_t qa[8][4];
#pragma unroll
    for (int kt = 0; kt < 8; kt++) {
        const float* q_lo = qkv + (size_t)(b * TT + r0) * 1536 + h * 64 + kt * 8;
        const float* q_hi = qkv + (size_t)(b * TT + r1) * 1536 + h * 64 + kt * 8;
        qa[kt][0] = f2tfu(q_lo[c]);
        qa[kt][1] = f2tfu(q_hi[c]);
        qa[kt][2] = f2tfu(q_lo[c + 4]);
        qa[kt][3] = f2tfu(q_hi[c + 4]);
    }

    float oacc[8][4];
#pragma unroll
    for (int nt = 0; nt < 8; nt++)
#pragma unroll
        for (int e = 0; e < 4; e++) oacc[nt][e] = 0.f;

    float m0 = -INFINITY, m1 = -INFINITY, l0 = 0.f, l1 = 0.f;
    const float scale = 0.125f;

    int csv[5]; int ncs = 0;
    const int offs[5] = {-64, 0, 64, 128, 192};
#pragma unroll
    for (int i = 0; i < 5; i++) {
        const int cs = q0 + offs[i];
        if (cs >= 0 && cs < TT) csv[ncs++] = cs;
    }

    const int lrow  = (tid >> 1) & 63;
    const int isv   = tid >> 7;
    const int lhalf = tid & 1;
    const uint32_t ldst0 = sptr((isv ? Vs : Ks) + lrow * KVP + lhalf * 32);
    const size_t lsrc_off = (size_t)512 + (size_t)isv * 512 + h * 64 + lhalf * 32;

    {
        const float* src = qkv + (size_t)(b * TT + csv[0] + lrow) * 1536 + lsrc_off;
#pragma unroll
        for (int i = 0; i < 8; i++) cpa16(ldst0 + i * 16, src + i * 4);
        CP_COMMIT();
    }

    const int srcA = (lane & 28) | (c >> 1);
    const int srcB = srcA + 2;
    const bool odd = (c & 1) != 0;

    for (int ci = 0; ci < ncs; ci++) {
        CP_WAIT(0);
        __syncthreads();

        if (ci + 1 < ncs) {
            const uint32_t dst = ldst0 + ((ci + 1) & 1) * ABUF * 4;
            const float* src = qkv + (size_t)(b * TT + csv[ci + 1] + lrow) * 1536 + lsrc_off;
#pragma unroll
            for (int i = 0; i < 8; i++) cpa16(dst + i * 16, src + i * 4);
            CP_COMMIT();
        }

        const int cs = csv[ci];
        const int lo_key = max(cs, w0 - PAST);
        const int hi_key = min(cs + 63, w0 + 15 + FUT);
        if (lo_key > hi_key) continue;
        const int ntlo = (lo_key - cs) >> 3;
        const int nthi = (hi_key - cs) >> 3;

        const float* Kb = Ks + (ci & 1) * ABUF;
        const float* Vb = Vs + (ci & 1) * ABUF;

        float sacc[8][4];
#pragma unroll
        for (int nt = 0; nt < 8; nt++) {
            sacc[nt][0] = 0.f; sacc[nt][1] = 0.f;
            sacc[nt][2] = 0.f; sacc[nt][3] = 0.f;
        }
#pragma unroll
        for (int nt = 0; nt < 8; nt++) {
            if (nt < ntlo || nt > nthi) continue;
#pragma unroll
            for (int kt = 0; kt < 8; kt++) {
                const uint32_t b0 = f2tfu(Kb[(nt * 8 + g) * KVP + kt * 8 + c]);
                const uint32_t b1 = f2tfu(Kb[(nt * 8 + g) * KVP + kt * 8 + c + 4]);
                MMA_TF32(sacc[nt][0], sacc[nt][1], sacc[nt][2], sacc[nt][3],
                         qa[kt][0], qa[kt][1], qa[kt][2], qa[kt][3], b0, b1);
            }
        }

        float mx0 = -INFINITY, mx1 = -INFINITY;
#pragma unroll
        for (int nt = 0; nt < 8; nt++) {
            if (nt < ntlo || nt > nthi) continue;
            const int j0 = cs + nt * 8 + 2 * c;
            const int j1 = j0 + 1;
            float v;
            v = sacc[nt][0] * scale;
            v = (j0 >= r0 - PAST && j0 <= r0 + FUT) ? v : -INFINITY;
            sacc[nt][0] = v; mx0 = fmaxf(mx0, v);
            v = sacc[nt][1] * scale;
            v = (j1 >= r0 - PAST && j1 <= r0 + FUT) ? v : -INFINITY;
            sacc[nt][1] = v; mx0 = fmaxf(mx0, v);
            v = sacc[nt][2] * scale;
            v = (j0 >= r1 - PAST && j0 <= r1 + FUT) ? v : -INFINITY;
            sacc[nt][2] = v; mx1 = fmaxf(mx1, v);
            v = sacc[nt][3] * scale;
            v = (j1 >= r1 - PAST && j1 <= r1 + FUT) ? v : -INFINITY;
            sacc[nt][3] = v; mx1 = fmaxf(mx1, v);
        }
        mx0 = fmaxf(mx0, __shfl_xor_sync(0xffffffffu, mx0, 1));
        mx0 = fmaxf(mx0, __shfl_xor_sync(0xffffffffu, mx0, 2));
        mx1 = fmaxf(mx1, __shfl_xor_sync(0xffffffffu, mx1, 1));
        mx1 = fmaxf(mx1, __shfl_xor_sync(0xffffffffu, mx1, 2));

        const float mn0 = fmaxf(m0, mx0);
        const float mn1 = fmaxf(m1, mx1);
        const float rf0 = __expf(fmaxf(m0 - mn0, -88.f));
        const float rf1 = __expf(fmaxf(m1 - mn1, -88.f));
        m0 = mn0; m1 = mn1;

        float ps0 = 0.f, ps1 = 0.f;
#pragma unroll
        for (int nt = 0; nt < 8; nt++) {
            if (nt < ntlo || nt > nthi) continue;
            const float p00 = __expf(fmaxf(sacc[nt][0] - mn0, -88.f));
            const float p01 = __expf(fmaxf(sacc[nt][1] - mn0, -88.f));
            const float p10 = __expf(fmaxf(sacc[nt][2] - mn1, -88.f));
            const float p11 = __expf(fmaxf(sacc[nt][3] - mn1, -88.f));
            ps0 += p00 + p01;
            ps1 += p10 + p11;
            sacc[nt][0] = f2tf(p00);
            sacc[nt][1] = f2tf(p01);
            sacc[nt][2] = f2tf(p10);
            sacc[nt][3] = f2tf(p11);
        }
        ps0 += __shfl_xor_sync(0xffffffffu, ps0, 1);
        ps0 += __shfl_xor_sync(0xffffffffu, ps0, 2);
        ps1 += __shfl_xor_sync(0xffffffffu, ps1, 1);
        ps1 += __shfl_xor_sync(0xffffffffu, ps1, 2);
        l0 = l0 * rf0 + ps0;
        l1 = l1 * rf1 + ps1;

#pragma unroll
        for (int nt = 0; nt < 8; nt++) {
            oacc[nt][0] *= rf0; oacc[nt][1] *= rf0;
            oacc[nt][2] *= rf1; oacc[nt][3] *= rf1;
        }

#pragma unroll
        for (int kt = 0; kt < 8; kt++) {
            if (kt < ntlo || kt > nthi) continue;
            float v00 = __shfl_sync(0xffffffffu, sacc[kt][0], srcA);
            float v01 = __shfl_sync(0xffffffffu, sacc[kt][1], srcA);
            float v10 = __shfl_sync(0xffffffffu, sacc[kt][2], srcA);
            float v11 = __shfl_sync(0xffffffffu, sacc[kt][3], srcA);
            const uint32_t a0 = __float_as_uint(odd ? v01 : v00);
            const uint32_t a1 = __float_as_uint(odd ? v11 : v10);
            v00 = __shfl_sync(0xffffffffu, sacc[kt][0], srcB);
            v01 = __shfl_sync(0xffffffffu, sacc[kt][1], srcB);
            v10 = __shfl_sync(0xffffffffu, sacc[kt][2], srcB);
            v11 = __shfl_sync(0xffffffffu, sacc[kt][3], srcB);
            const uint32_t a2 = __float_as_uint(odd ? v01 : v00);
            const uint32_t a3 = __float_as_uint(odd ? v11 : v10);
#pragma unroll
            for (int nt = 0; nt < 8; nt++) {
                const uint32_t b0 = f2tfu(Vb[(kt * 8 + c    ) * KVP + nt * 8 + g]);
                const uint32_t b1 = f2tfu(Vb[(kt * 8 + c + 4) * KVP + nt * 8 + g]);
                MMA_TF32(oacc[nt][0], oacc[nt][1], oacc[nt][2], oacc[nt][3],
                         a0, a1, a2, a3, b0, b1);
            }
        }
    }

    const float inv0 = 1.f / l0, inv1 = 1.f / l1;
#pragma unroll
    for (int nt = 0; nt < 8; nt++) {
        const int col = h * 64 + nt * 8 + 2 * c;
        float2 w;
        w.x = oacc[nt][0] * inv0; w.y = oacc[nt][1] * inv0;
        *(float2*)(ctx + (size_t)(b * TT + r0) * DD + col) = w;
        w.x = oacc[nt][2] * inv1; w.y = oacc[nt][3] * inv1;
        *(float2*)(ctx + (size_t)(b * TT + r1) * DD + col) = w;
    }
}

// ---------------- residual add + LayerNorm ----------------------------------
__global__ __launch_bounds__(128)
void add_ln(const float* __restrict__ x, const float* __restrict__ y,
            const float* __restrict__ s, const float* __restrict__ bta,
            float* __restrict__ out)
{
    const int row = blockIdx.x;
    const int tid = threadIdx.x;
    float v[4];
    float sum = 0.f, sq = 0.f;
#pragma unroll
    for (int i = 0; i < 4; i++) {
        int c = tid + i * 128;
        float val = x[(size_t)row * DD + c] + y[(size_t)row * DD + c];
        v[i] = val;
        sum += val;
        sq  += val * val;
    }
    __shared__ float rs[8];
#pragma unroll
    for (int off = 16; off > 0; off >>= 1) {
        sum += __shfl_xor_sync(0xffffffffu, sum, off);
        sq  += __shfl_xor_sync(0xffffffffu, sq,  off);
    }
    if ((tid & 31) == 0) { rs[tid >> 5] = sum; rs[4 + (tid >> 5)] = sq; }
    __syncthreads();
    sum = rs[0] + rs[1] + rs[2] + rs[3];
    sq  = rs[4] + rs[5] + rs[6] + rs[7];
    const float mean = sum * (1.f / DD);
    const float var  = sq * (1.f / DD) - mean * mean;
    const float inv  = rsqrtf(var + EPS);
#pragma unroll
    for (int i = 0; i < 4; i++) {
        int c = tid + i * 128;
        out[(size_t)row * DD + c] = (v[i] - mean) * inv * s[c] + bta[c];
    }
}

// ---------------- mean pool (two-stage) -------------------------------------
__global__ void pool_partial(const float* __restrict__ emb, float* __restrict__ pp)
{
    const int b = blockIdx.x >> 5, ch = blockIdx.x & 31;
    const int d = threadIdx.x;
    float s = 0.f;
    const int t0 = ch * 64;
    for (int t = t0; t < t0 + 64; t++)
        s += emb[((size_t)(b * TT + t)) * DD + d];
    pp[(size_t)blockIdx.x * DD + d] = s;
}

__global__ void pool_reduce(const float* __restrict__ pp, float* __restrict__ p)
{
    const int b = blockIdx.x, d = threadIdx.x;
    float s = 0.f;
    for (int ch = 0; ch < 32; ch++)
        s += pp[(size_t)(b * 32 + ch) * DD + d];
    p[b * DD + d] = s * (1.f / TT);
}

// ---------------- tiny dense layer (heads) ----------------------------------
__global__ void small_linear(const float* __restrict__ in, const float* __restrict__ W,
                             const float* __restrict__ bias, float* __restrict__ out,
                             int K, int N, int relu)
{
    const int b = blockIdx.x, n = threadIdx.x;
    if (n >= N) return;
    float sum = bias[n];
    for (int k = 0; k < K; k++)
        sum = fmaf(in[b * K + k], W[(size_t)k * N + n], sum);
    if (relu) sum = fmaxf(sum, 0.f);
    out[b * N + n] = sum;
}

// ---------------- launch -----------------------------------------------------
extern "C" void kernel_launch(void* const* d_in, const int* in_sizes, int n_in,
                              void* d_out, int out_size)
{
    const float* feats  = (const float*)d_in[0];
    const float* projW  = (const float*)d_in[1];
    const float* projB  = (const float*)d_in[2];
    const float* posenc = (const float*)d_in[3];
    const float* qkvW   = (const float*)d_in[4];
    const float* qkvB   = (const float*)d_in[5];
    const float* outW   = (const float*)d_in[6];
    const float* outB   = (const float*)d_in[7];
    const float* ln1s   = (const float*)d_in[8];
    const float* ln1b   = (const float*)d_in[9];
    const float* ff1W   = (const float*)d_in[10];
    const float* ff1B   = (const float*)d_in[11];
    const float* ff2W   = (const float*)d_in[12];
    const float* ff2B   = (const float*)d_in[13];
    const float* ln2s   = (const float*)d_in[14];
    const float* ln2b   = (const float*)d_in[15];
    const float* mu1W   = (const float*)d_in[16];
    const float* mu1B   = (const float*)d_in[17];
    const float* mu2W   = (const float*)d_in[18];
    const float* mu2B   = (const float*)d_in[19];
    const float* lv1W   = (const float*)d_in[20];
    const float* lv1B   = (const float*)d_in[21];
    const float* lv2W   = (const float*)d_in[22];
    const float* lv2B   = (const float*)d_in[23];

    float *px, *pqkv, *pctx, *ptmp, *pff, *ppool, *ppp, *ph;
    cudaGetSymbolAddress((void**)&px,    g_x);
    cudaGetSymbolAddress((void**)&pqkv,  g_qkv);
    cudaGetSymbolAddress((void**)&pctx,  g_ctx);
    cudaGetSymbolAddress((void**)&ptmp,  g_tmp);
    cudaGetSymbolAddress((void**)&pff,   g_ff);
    cudaGetSymbolAddress((void**)&ppool, g_pool);
    cudaGetSymbolAddress((void**)&ppp,   g_pp);
    cudaGetSymbolAddress((void**)&ph,    g_h);

    cudaFuncSetAttribute(attn_mma, cudaFuncAttributeMaxDynamicSharedMemorySize, ATTN_SMEM);

    float* emb = (float*)d_out;
    float* mu  = emb + (size_t)ROWS * DD;
    float* lv  = mu + BB * LAT;

    // x = feats @ projW + projB + posenc
    {
        dim3 grid(DD / 128, ROWS / 128);
        gemm_f16<2><<<grid, 256>>>(feats, projW, projB, posenc, px, ROWS, DD, INF_);
    }

    for (int l = 0; l < LL; l++) {
        {
            dim3 grid((3 * DD) / 128, ROWS / 128);
            gemm_f16<0><<<grid, 256>>>(px, qkvW + (size_t)l * DD * 3 * DD,
                                       qkvB + l * 3 * DD, nullptr, pqkv,
                                       ROWS, 3 * DD, DD);
        }
        attn_mma<<<BB * HH * 16, 256, ATTN_SMEM>>>(pqkv, pctx);
        {
            dim3 grid(DD / 128, ROWS / 128);
            gemm_f16<0><<<grid, 256>>>(pctx, outW + (size_t)l * DD * DD,
                                       outB + l * DD, nullptr, ptmp, ROWS, DD, DD);
        }
        add_ln<<<ROWS, 128>>>(px, ptmp, ln1s + l * DD, ln1b + l * DD, px);
        {
            dim3 grid(FF_ / 128, ROWS / 128);
            gemm_f16<1><<<grid, 256>>>(px, ff1W + (size_t)l * DD * FF_,
                                       ff1B + l * FF_, nullptr, pff, ROWS, FF_, DD);
        }
        {
            dim3 grid(DD / 128, ROWS / 128);
            gemm_f16<0><<<grid, 256>>>(pff, ff2W + (size_t)l * FF_ * DD,
                                       ff2B + l * DD, nullptr, ptmp, ROWS, DD, FF_);
        }
        float* dst = (l == LL - 1) ? emb : px;
        add_ln<<<ROWS, 128>>>(px, ptmp, ln2s + l * DD, ln2b + l * DD, dst);
    }

    pool_partial<<<BB * 32, DD>>>(emb, ppp);
    pool_reduce<<<BB, DD>>>(ppp, ppool);
    small_linear<<<BB, 2 * LAT>>>(ppool, mu1W, mu1B, ph, DD, 2 * LAT, 1);
    small_linear<<<BB, LAT>>>(ph, mu2W, mu2B, mu, 2 * LAT, LAT, 0);
    small_linear<<<BB, 2 * LAT>>>(ppool, lv1W, lv1B, ph, DD, 2 * LAT, 1);
    small_linear<<<BB, LAT>>>(ph, lv2W, lv2B, lv, 2 * LAT, LAT, 0);
}

// round 11
// speedup vs baseline: 2.7344x; 1.3851x over previous
#include <cuda_runtime.h>
#include <cuda_fp16.h>
#include <math.h>
#include <stdint.h>

// Problem constants
#define BB 4
#define TT 2048
#define INF_ 64
#define DD 512
#define HH 8
#define DH 64
#define FF_ 2048
#define LL 4
#define LAT 128
#define PAST 40
#define FUT 120
#define ROWS (BB*TT)          // 8192
#define EPS 1e-5f

// ---------------- scratch (device globals; no allocation allowed) ----------
__device__ float   g_x   [ROWS * DD];
__device__ float   g_qkv [ROWS * 3 * DD];
__device__ float   g_tmp [ROWS * DD];
__device__ float   g_pool[BB * DD];
__device__ float   g_pp  [BB * 32 * DD];
__device__ float   g_h   [BB * 2 * LAT];
__device__ __half  g_xh  [ROWS * DD];      // half mirror of x (GEMM A)
__device__ __half  g_ctxh[ROWS * DD];      // attention output (half)
__device__ __half  g_ffh [ROWS * FF_];     // ff1 output (half)
__device__ __half  g_fh  [ROWS * INF_];    // feats (half)
__device__ uint32_t g_wh [6307840];        // all weights k-pair-packed half2

// word offsets into g_wh
#define WH_PROJ 0
#define WH_QKV  16384
#define WH_OUT  1589248
#define WH_FF1  2113536
#define WH_FF2  4210688

// ---------------- helpers ---------------------------------------------------
__device__ __forceinline__ float f2tf(float x) {
    uint32_t u; asm("cvt.rna.tf32.f32 %0, %1;" : "=r"(u) : "f"(x));
    return __uint_as_float(u);
}
__device__ __forceinline__ uint32_t f2tfu(float x) {
    uint32_t u; asm("cvt.rna.tf32.f32 %0, %1;" : "=r"(u) : "f"(x));
    return u;
}
__device__ __forceinline__ uint32_t sptr(const void* p) {
    return (uint32_t)__cvta_generic_to_shared(p);
}
__device__ __forceinline__ void cpa16(uint32_t dst, const void* src) {
    asm volatile("cp.async.cg.shared.global [%0], [%1], 16;\n" :: "r"(dst), "l"(src));
}
#define CP_COMMIT() asm volatile("cp.async.commit_group;\n")
#define CP_WAIT(n)  asm volatile("cp.async.wait_group %0;\n" :: "n"(n))

#define MMA_TF32(d0,d1,d2,d3,a0,a1,a2,a3,b0,b1)                              \
    asm volatile("mma.sync.aligned.m16n8k8.row.col.f32.tf32.tf32.f32 "       \
        "{%0,%1,%2,%3},{%4,%5,%6,%7},{%8,%9},{%0,%1,%2,%3};"                 \
        : "+f"(d0),"+f"(d1),"+f"(d2),"+f"(d3)                                \
        : "r"(a0),"r"(a1),"r"(a2),"r"(a3),"r"(b0),"r"(b1))

#define MMA_F16(d0,d1,d2,d3,a0,a1,a2,a3,b0,b1)                               \
    asm volatile("mma.sync.aligned.m16n8k16.row.col.f32.f16.f16.f32 "        \
        "{%0,%1,%2,%3},{%4,%5,%6,%7},{%8,%9},{%0,%1,%2,%3};"                 \
        : "+f"(d0),"+f"(d1),"+f"(d2),"+f"(d3)                                \
        : "r"(a0),"r"(a1),"r"(a2),"r"(a3),"r"(b0),"r"(b1))

// ---------------- weight pack: Wp[kp][n] = {h(W[2kp][n]), h(W[2kp+1][n])} ---
__global__ void pack_w(const float* __restrict__ W, uint32_t* __restrict__ Wp,
                       int K, int N)
{
    const int wpl = (K >> 1) * N;   // words per layer
    const float* Wz = W + (size_t)blockIdx.z * K * N;
    uint32_t* Wpz = Wp + (size_t)blockIdx.z * wpl;
    const int w = blockIdx.x * 256 + threadIdx.x;
    if (w >= wpl) return;
    const int kp = w / N, n = w - kp * N;
    __half2 h = __floats2half2_rn(Wz[(size_t)(2 * kp) * N + n],
                                  Wz[(size_t)(2 * kp + 1) * N + n]);
    Wpz[w] = *reinterpret_cast<uint32_t*>(&h);
}

// ---------------- f32 -> half convert ---------------------------------------
__global__ void conv_half(const float* __restrict__ in, __half* __restrict__ out,
                          int n2)
{
    const int i = blockIdx.x * 256 + threadIdx.x;
    if (i >= n2) return;
    const float2 v = ((const float2*)in)[i];
    ((__half2*)out)[i] = __floats2half2_rn(v.x, v.y);
}

// ---------------- FP16 GEMM, cp.async 3-stage, pre-packed operands ----------
// C[M,N] = A[M,K] @ B[K,N] + bias. BM=BN=128, BK=32, 8 warps.
// A: half row-major (raw pairs = a-frag words). Bp: packed k-pair words.
// EPI: 0 = +bias -> C(f32) ; 1 = +bias,relu -> Ch(half) ;
//      2 = +bias+posenc -> C(f32) AND Ch(half)
#define AP2 20
#define BP2 136
#define GH_ASZ (128 * AP2)              // words per A stage
#define GH_BSZ (16 * BP2)               // words per B stage
#define GH_SMEM (3 * (GH_ASZ + GH_BSZ) * 4)   // 56832 B

template <int EPI>
__global__ __launch_bounds__(256, 2)
void gemm_h(const __half* __restrict__ A, const uint32_t* __restrict__ Bp,
            const float* __restrict__ bias, const float* __restrict__ extra,
            float* __restrict__ C, __half* __restrict__ Ch, int N, int K)
{
    extern __shared__ uint32_t smw[];
    uint32_t* As = smw;                  // [3][128][20]
    uint32_t* Bs = smw + 3 * GH_ASZ;     // [3][16][136]

    const int tid  = threadIdx.x;
    const int wid  = tid >> 5, lane = tid & 31;
    const int g    = lane >> 2, c = lane & 3;
    const int wm   = (wid >> 2) * 64;
    const int wn   = (wid & 3) * 32;
    const int brow = blockIdx.y * 128, bcol = blockIdx.x * 128;

    // A loader: row = tid>>1, half16B chunk pair sel = tid&1 (covers kp 8ch..8ch+7)
    const int arow = tid >> 1, ach = tid & 1;
    // B loader: kp-row = tid>>4 (0..15), n0 = (tid&15)*8
    const int bkr = tid >> 4, bn0 = (tid & 15) * 8;

    const __half* Ag = A + (size_t)(brow + arow) * K + ach * 16;
    const uint32_t* Bg = Bp + bcol + bn0 + (size_t)bkr * N;

    const uint32_t sA = sptr(As) + (uint32_t)(arow * AP2 + ach * 8) * 4u;
    const uint32_t sB = sptr(Bs) + (uint32_t)(bkr * BP2 + bn0) * 4u;

    float acc[4][4][4];
#pragma unroll
    for (int i = 0; i < 4; i++)
#pragma unroll
        for (int j = 0; j < 4; j++)
#pragma unroll
            for (int r = 0; r < 4; r++) acc[i][j][r] = 0.f;

    const int nk = K >> 5;   // BK = 32 (16 k-pairs)

    // prologue: stages 0, 1
    {
        cpa16(sA, Ag);  cpa16(sA + 16, Ag + 8);
        cpa16(sB, Bg);  cpa16(sB + 16, Bg + 4);
        CP_COMMIT();
        if (nk > 1) {
            cpa16(sA + GH_ASZ * 4, Ag + 32);
            cpa16(sA + GH_ASZ * 4 + 16, Ag + 40);
            cpa16(sB + GH_BSZ * 4, Bg + (size_t)16 * N);
            cpa16(sB + GH_BSZ * 4 + 16, Bg + (size_t)16 * N + 4);
            CP_COMMIT();
            CP_WAIT(1);
        } else {
            CP_WAIT(0);
        }
        __syncthreads();
    }

    int s_cur = 0;
    for (int s = 0; s < nk; s++) {
        if (s + 2 < nk) {
            const int sl = (s_cur + 2 >= 3) ? s_cur - 1 : s_cur + 2;
            const __half* ga = Ag + (size_t)(s + 2) * 32;
            cpa16(sA + sl * GH_ASZ * 4, ga);
            cpa16(sA + sl * GH_ASZ * 4 + 16, ga + 8);
            const uint32_t* gb = Bg + (size_t)(s + 2) * 16 * N;
            cpa16(sB + sl * GH_BSZ * 4, gb);
            cpa16(sB + sl * GH_BSZ * 4 + 16, gb + 4);
            CP_COMMIT();
        }

        const uint32_t* Ab = As + s_cur * GH_ASZ;
        const uint32_t* Bb = Bs + s_cur * GH_BSZ;
#pragma unroll
        for (int kk = 0; kk < 2; kk++) {
            uint32_t af[4][4];
#pragma unroll
            for (int mt = 0; mt < 4; mt++) {
                const int m0 = wm + mt * 16 + g;
                af[mt][0] = Ab[(m0    ) * AP2 + kk * 8 + c];
                af[mt][1] = Ab[(m0 + 8) * AP2 + kk * 8 + c];
                af[mt][2] = Ab[(m0    ) * AP2 + kk * 8 + c + 4];
                af[mt][3] = Ab[(m0 + 8) * AP2 + kk * 8 + c + 4];
            }
            uint32_t bf[4][2];
#pragma unroll
            for (int nt = 0; nt < 4; nt++) {
                const int n0 = wn + nt * 8 + g;
                bf[nt][0] = Bb[(kk * 8 + c    ) * BP2 + n0];
                bf[nt][1] = Bb[(kk * 8 + c + 4) * BP2 + n0];
            }
#pragma unroll
            for (int mt = 0; mt < 4; mt++)
#pragma unroll
                for (int nt = 0; nt < 4; nt++)
                    MMA_F16(acc[mt][nt][0], acc[mt][nt][1], acc[mt][nt][2], acc[mt][nt][3],
                            af[mt][0], af[mt][1], af[mt][2], af[mt][3],
                            bf[nt][0], bf[nt][1]);
        }

        if (s + 1 < nk) {
            if (s + 2 < nk) CP_WAIT(1); else CP_WAIT(0);
            __syncthreads();
        }
        s_cur = (s_cur + 1 >= 3) ? 0 : s_cur + 1;
    }

    // epilogue: frag (row g/g+8, col 2c/2c+1)
#pragma unroll
    for (int mt = 0; mt < 4; mt++) {
#pragma unroll
        for (int nt = 0; nt < 4; nt++) {
            const int col = bcol + wn + nt * 8 + 2 * c;
            const float b0 = bias[col], b1 = bias[col + 1];
#pragma unroll
            for (int half = 0; half < 2; half++) {
                const int row = brow + wm + mt * 16 + g + half * 8;
                float v0 = acc[mt][nt][half * 2 + 0] + b0;
                float v1 = acc[mt][nt][half * 2 + 1] + b1;
                if (EPI == 1) {
                    v0 = fmaxf(v0, 0.f); v1 = fmaxf(v1, 0.f);
                    *(__half2*)(Ch + (size_t)row * N + col) = __floats2half2_rn(v0, v1);
                } else {
                    if (EPI == 2) {
                        const int t = row & (TT - 1);
                        v0 += extra[(size_t)t * N + col];
                        v1 += extra[(size_t)t * N + col + 1];
                        *(__half2*)(Ch + (size_t)row * N + col) = __floats2half2_rn(v0, v1);
                    }
                    float2 o; o.x = v0; o.y = v1;
                    *(float2*)(C + (size_t)row * N + col) = o;
                }
            }
        }
    }
}

// ---------------- banded flash attention (round-5 proven; half output) ------
#define KVP 72
#define ABUF (64 * KVP)
#define ATTN_SMEM (4 * ABUF * 4)

__global__ __launch_bounds__(256, 2)
void attn_mma(const float* __restrict__ qkv, __half* __restrict__ ctxh)
{
    extern __shared__ float sm[];
    float* Ks = sm;
    float* Vs = sm + 2 * ABUF;

    const int blk = blockIdx.x;
    const int qt = blk & 15;
    const int h  = (blk >> 4) & 7;
    const int b  = blk >> 7;
    const int q0 = qt * 128;

    const int tid = threadIdx.x, wid = tid >> 5, lane = tid & 31;
    const int g = lane >> 2, c = lane & 3;
    const int w0 = q0 + wid * 16;
    const int r0 = w0 + g, r1 = r0 + 8;

    uint32_t qa[8][4];
#pragma unroll
    for (int kt = 0; kt < 8; kt++) {
        const float* q_lo = qkv + (size_t)(b * TT + r0) * 1536 + h * 64 + kt * 8;
        const float* q_hi = qkv + (size_t)(b * TT + r1) * 1536 + h * 64 + kt * 8;
        qa[kt][0] = f2tfu(q_lo[c]);
        qa[kt][1] = f2tfu(q_hi[c]);
        qa[kt][2] = f2tfu(q_lo[c + 4]);
        qa[kt][3] = f2tfu(q_hi[c + 4]);
    }

    float oacc[8][4];
#pragma unroll
    for (int nt = 0; nt < 8; nt++)
#pragma unroll
        for (int e = 0; e < 4; e++) oacc[nt][e] = 0.f;

    float m0 = -INFINITY, m1 = -INFINITY, l0 = 0.f, l1 = 0.f;
    const float scale = 0.125f;

    int csv[5]; int ncs = 0;
    const int offs[5] = {-64, 0, 64, 128, 192};
#pragma unroll
    for (int i = 0; i < 5; i++) {
        const int cs = q0 + offs[i];
        if (cs >= 0 && cs < TT) csv[ncs++] = cs;
    }

    const int lrow  = (tid >> 1) & 63;
    const int isv   = tid >> 7;
    const int lhalf = tid & 1;
    const uint32_t ldst0 = sptr((isv ? Vs : Ks) + lrow * KVP + lhalf * 32);
    const size_t lsrc_off = (size_t)512 + (size_t)isv * 512 + h * 64 + lhalf * 32;

    {
        const float* src = qkv + (size_t)(b * TT + csv[0] + lrow) * 1536 + lsrc_off;
#pragma unroll
        for (int i = 0; i < 8; i++) cpa16(ldst0 + i * 16, src + i * 4);
        CP_COMMIT();
    }

    const int srcA = (lane & 28) | (c >> 1);
    const int srcB = srcA + 2;
    const bool odd = (c & 1) != 0;

    for (int ci = 0; ci < ncs; ci++) {
        CP_WAIT(0);
        __syncthreads();

        if (ci + 1 < ncs) {
            const uint32_t dst = ldst0 + ((ci + 1) & 1) * ABUF * 4;
            const float* src = qkv + (size_t)(b * TT + csv[ci + 1] + lrow) * 1536 + lsrc_off;
#pragma unroll
            for (int i = 0; i < 8; i++) cpa16(dst + i * 16, src + i * 4);
            CP_COMMIT();
        }

        const int cs = csv[ci];
        const int lo_key = max(cs, w0 - PAST);
        const int hi_key = min(cs + 63, w0 + 15 + FUT);
        if (lo_key > hi_key) continue;
        const int ntlo = (lo_key - cs) >> 3;
        const int nthi = (hi_key - cs) >> 3;

        const float* Kb = Ks + (ci & 1) * ABUF;
        const float* Vb = Vs + (ci & 1) * ABUF;

        float sacc[8][4];
#pragma unroll
        for (int nt = 0; nt < 8; nt++) {
            sacc[nt][0] = 0.f; sacc[nt][1] = 0.f;
            sacc[nt][2] = 0.f; sacc[nt][3] = 0.f;
        }
#pragma unroll
        for (int nt = 0; nt < 8; nt++) {
            if (nt < ntlo || nt > nthi) continue;
#pragma unroll
            for (int kt = 0; kt < 8; kt++) {
                const uint32_t b0 = f2tfu(Kb[(nt * 8 + g) * KVP + kt * 8 + c]);
                const uint32_t b1 = f2tfu(Kb[(nt * 8 + g) * KVP + kt * 8 + c + 4]);
                MMA_TF32(sacc[nt][0], sacc[nt][1], sacc[nt][2], sacc[nt][3],
                         qa[kt][0], qa[kt][1], qa[kt][2], qa[kt][3], b0, b1);
            }
        }

        float mx0 = -INFINITY, mx1 = -INFINITY;
#pragma unroll
        for (int nt = 0; nt < 8; nt++) {
            if (nt < ntlo || nt > nthi) continue;
            const int j0 = cs + nt * 8 + 2 * c;
            const int j1 = j0 + 1;
            float v;
            v = sacc[nt][0] * scale;
            v = (j0 >= r0 - PAST && j0 <= r0 + FUT) ? v : -INFINITY;
            sacc[nt][0] = v; mx0 = fmaxf(mx0, v);
            v = sacc[nt][1] * scale;
            v = (j1 >= r0 - PAST && j1 <= r0 + FUT) ? v : -INFINITY;
            sacc[nt][1] = v; mx0 = fmaxf(mx0, v);
            v = sacc[nt][2] * scale;
            v = (j0 >= r1 - PAST && j0 <= r1 + FUT) ? v : -INFINITY;
            sacc[nt][2] = v; mx1 = fmaxf(mx1, v);
            v = sacc[nt][3] * scale;
            v = (j1 >= r1 - PAST && j1 <= r1 + FUT) ? v : -INFINITY;
            sacc[nt][3] = v; mx1 = fmaxf(mx1, v);
        }
        mx0 = fmaxf(mx0, __shfl_xor_sync(0xffffffffu, mx0, 1));
        mx0 = fmaxf(mx0, __shfl_xor_sync(0xffffffffu, mx0, 2));
        mx1 = fmaxf(mx1, __shfl_xor_sync(0xffffffffu, mx1, 1));
        mx1 = fmaxf(mx1, __shfl_xor_sync(0xffffffffu, mx1, 2));

        const float mn0 = fmaxf(m0, mx0);
        const float mn1 = fmaxf(m1, mx1);
        const float rf0 = __expf(fmaxf(m0 - mn0, -88.f));
        const float rf1 = __expf(fmaxf(m1 - mn1, -88.f));
        m0 = mn0; m1 = mn1;

        float ps0 = 0.f, ps1 = 0.f;
#pragma unroll
        for (int nt = 0; nt < 8; nt++) {
            if (nt < ntlo || nt > nthi) continue;
            const float p00 = __expf(fmaxf(sacc[nt][0] - mn0, -88.f));
            const float p01 = __expf(fmaxf(sacc[nt][1] - mn0, -88.f));
            const float p10 = __expf(fmaxf(sacc[nt][2] - mn1, -88.f));
            const float p11 = __expf(fmaxf(sacc[nt][3] - mn1, -88.f));
            ps0 += p00 + p01;
            ps1 += p10 + p11;
            sacc[nt][0] = f2tf(p00);
            sacc[nt][1] = f2tf(p01);
            sacc[nt][2] = f2tf(p10);
            sacc[nt][3] = f2tf(p11);
        }
        ps0 += __shfl_xor_sync(0xffffffffu, ps0, 1);
        ps0 += __shfl_xor_sync(0xffffffffu, ps0, 2);
        ps1 += __shfl_xor_sync(0xffffffffu, ps1, 1);
        ps1 += __shfl_xor_sync(0xffffffffu, ps1, 2);
        l0 = l0 * rf0 + ps0;
        l1 = l1 * rf1 + ps1;

#pragma unroll
        for (int nt = 0; nt < 8; nt++) {
            oacc[nt][0] *= rf0; oacc[nt][1] *= rf0;
            oacc[nt][2] *= rf1; oacc[nt][3] *= rf1;
        }

#pragma unroll
        for (int kt = 0; kt < 8; kt++) {
            if (kt < ntlo || kt > nthi) continue;
            float v00 = __shfl_sync(0xffffffffu, sacc[kt][0], srcA);
            float v01 = __shfl_sync(0xffffffffu, sacc[kt][1], srcA);
            float v10 = __shfl_sync(0xffffffffu, sacc[kt][2], srcA);
            float v11 = __shfl_sync(0xffffffffu, sacc[kt][3], srcA);
            const uint32_t a0 = __float_as_uint(odd ? v01 : v00);
            const uint32_t a1 = __float_as_uint(odd ? v11 : v10);
            v00 = __shfl_sync(0xffffffffu, sacc[kt][0], srcB);
            v01 = __shfl_sync(0xffffffffu, sacc[kt][1], srcB);
            v10 = __shfl_sync(0xffffffffu, sacc[kt][2], srcB);
            v11 = __shfl_sync(0xffffffffu, sacc[kt][3], srcB);
            const uint32_t a2 = __float_as_uint(odd ? v01 : v00);
            const uint32_t a3 = __float_as_uint(odd ? v11 : v10);
#pragma unroll
            for (int nt = 0; nt < 8; nt++) {
                const uint32_t b0 = f2tfu(Vb[(kt * 8 + c    ) * KVP + nt * 8 + g]);
                const uint32_t b1 = f2tfu(Vb[(kt * 8 + c + 4) * KVP + nt * 8 + g]);
                MMA_TF32(oacc[nt][0], oacc[nt][1], oacc[nt][2], oacc[nt][3],
                         a0, a1, a2, a3, b0, b1);
            }
        }
    }

    const float inv0 = 1.f / l0, inv1 = 1.f / l1;
#pragma unroll
    for (int nt = 0; nt < 8; nt++) {
        const int col = h * 64 + nt * 8 + 2 * c;
        *(__half2*)(ctxh + (size_t)(b * TT + r0) * DD + col) =
            __floats2half2_rn(oacc[nt][0] * inv0, oacc[nt][1] * inv0);
        *(__half2*)(ctxh + (size_t)(b * TT + r1) * DD + col) =
            __floats2half2_rn(oacc[nt][2] * inv1, oacc[nt][3] * inv1);
    }
}

// ---------------- residual add + LayerNorm (optional half mirror) -----------
template <int WRH>
__global__ __launch_bounds__(128)
void add_ln(const float* __restrict__ x, const float* __restrict__ y,
            const float* __restrict__ s, const float* __restrict__ bta,
            float* __restrict__ out, __half* __restrict__ outh)
{
    const int row = blockIdx.x;
    const int tid = threadIdx.x;
    float v[4];
    float sum = 0.f, sq = 0.f;
#pragma unroll
    for (int i = 0; i < 4; i++) {
        int c = tid + i * 128;
        float val = x[(size_t)row * DD + c] + y[(size_t)row * DD + c];
        v[i] = val;
        sum += val;
        sq  += val * val;
    }
    __shared__ float rs[8];
#pragma unroll
    for (int off = 16; off > 0; off >>= 1) {
        sum += __shfl_xor_sync(0xffffffffu, sum, off);
        sq  += __shfl_xor_sync(0xffffffffu, sq,  off);
    }
    if ((tid & 31) == 0) { rs[tid >> 5] = sum; rs[4 + (tid >> 5)] = sq; }
    __syncthreads();
    sum = rs[0] + rs[1] + rs[2] + rs[3];
    sq  = rs[4] + rs[5] + rs[6] + rs[7];
    const float mean = sum * (1.f / DD);
    const float var  = sq * (1.f / DD) - mean * mean;
    const float inv  = rsqrtf(var + EPS);
#pragma unroll
    for (int i = 0; i < 4; i++) {
        int c = tid + i * 128;
        const float o = (v[i] - mean) * inv * s[c] + bta[c];
        out[(size_t)row * DD + c] = o;
        if (WRH) outh[(size_t)row * DD + c] = __float2half_rn(o);
    }
}

// ---------------- mean pool (two-stage) -------------------------------------
__global__ void pool_partial(const float* __restrict__ emb, float* __restrict__ pp)
{
    const int b = blockIdx.x >> 5, ch = blockIdx.x & 31;
    const int d = threadIdx.x;
    float s = 0.f;
    const int t0 = ch * 64;
    for (int t = t0; t < t0 + 64; t++)
        s += emb[((size_t)(b * TT + t)) * DD + d];
    pp[(size_t)blockIdx.x * DD + d] = s;
}

__global__ void pool_reduce(const float* __restrict__ pp, float* __restrict__ p)
{
    const int b = blockIdx.x, d = threadIdx.x;
    float s = 0.f;
    for (int ch = 0; ch < 32; ch++)
        s += pp[(size_t)(b * 32 + ch) * DD + d];
    p[b * DD + d] = s * (1.f / TT);
}

// ---------------- tiny dense layer (heads) ----------------------------------
__global__ void small_linear(const float* __restrict__ in, const float* __restrict__ W,
                             const float* __restrict__ bias, float* __restrict__ out,
                             int K, int N, int relu)
{
    const int b = blockIdx.x, n = threadIdx.x;
    if (n >= N) return;
    float sum = bias[n];
    for (int k = 0; k < K; k++)
        sum = fmaf(in[b * K + k], W[(size_t)k * N + n], sum);
    if (relu) sum = fmaxf(sum, 0.f);
    out[b * N + n] = sum;
}

// ---------------- launch -----------------------------------------------------
extern "C" void kernel_launch(void* const* d_in, const int* in_sizes, int n_in,
                              void* d_out, int out_size)
{
    const float* feats  = (const float*)d_in[0];
    const float* projW  = (const float*)d_in[1];
    const float* projB  = (const float*)d_in[2];
    const float* posenc = (const float*)d_in[3];
    const float* qkvW   = (const float*)d_in[4];
    const float* qkvB   = (const float*)d_in[5];
    const float* outW   = (const float*)d_in[6];
    const float* outB   = (const float*)d_in[7];
    const float* ln1s   = (const float*)d_in[8];
    const float* ln1b   = (const float*)d_in[9];
    const float* ff1W   = (const float*)d_in[10];
    const float* ff1B   = (const float*)d_in[11];
    const float* ff2W   = (const float*)d_in[12];
    const float* ff2B   = (const float*)d_in[13];
    const float* ln2s   = (const float*)d_in[14];
    const float* ln2b   = (const float*)d_in[15];
    const float* mu1W   = (const float*)d_in[16];
    const float* mu1B   = (const float*)d_in[17];
    const float* mu2W   = (const float*)d_in[18];
    const float* mu2B   = (const float*)d_in[19];
    const float* lv1W   = (const float*)d_in[20];
    const float* lv1B   = (const float*)d_in[21];
    const float* lv2W   = (const float*)d_in[22];
    const float* lv2B   = (const float*)d_in[23];

    float *px, *pqkv, *ptmp, *ppool, *ppp, *ph;
    __half *pxh, *pctxh, *pffh, *pfh;
    uint32_t* pwh;
    cudaGetSymbolAddress((void**)&px,    g_x);
    cudaGetSymbolAddress((void**)&pqkv,  g_qkv);
    cudaGetSymbolAddress((void**)&ptmp,  g_tmp);
    cudaGetSymbolAddress((void**)&ppool, g_pool);
    cudaGetSymbolAddress((void**)&ppp,   g_pp);
    cudaGetSymbolAddress((void**)&ph,    g_h);
    cudaGetSymbolAddress((void**)&pxh,   g_xh);
    cudaGetSymbolAddress((void**)&pctxh, g_ctxh);
    cudaGetSymbolAddress((void**)&pffh,  g_ffh);
    cudaGetSymbolAddress((void**)&pfh,   g_fh);
    cudaGetSymbolAddress((void**)&pwh,   g_wh);

    cudaFuncSetAttribute(gemm_h<0>, cudaFuncAttributeMaxDynamicSharedMemorySize, GH_SMEM);
    cudaFuncSetAttribute(gemm_h<1>, cudaFuncAttributeMaxDynamicSharedMemorySize, GH_SMEM);
    cudaFuncSetAttribute(gemm_h<2>, cudaFuncAttributeMaxDynamicSharedMemorySize, GH_SMEM);
    cudaFuncSetAttribute(attn_mma,  cudaFuncAttributeMaxDynamicSharedMemorySize, ATTN_SMEM);

    float* emb = (float*)d_out;
    float* mu  = emb + (size_t)ROWS * DD;
    float* lv  = mu + BB * LAT;

    // ---- pre-pack weights + convert feats
    pack_w<<<dim3(64, 1, 1),    256>>>(projW, pwh + WH_PROJ, 64, 512);
    pack_w<<<dim3(1536, 1, 4),  256>>>(qkvW,  pwh + WH_QKV,  512, 1536);
    pack_w<<<dim3(512, 1, 4),   256>>>(outW,  pwh + WH_OUT,  512, 512);
    pack_w<<<dim3(2048, 1, 4),  256>>>(ff1W,  pwh + WH_FF1,  512, 2048);
    pack_w<<<dim3(2048, 1, 4),  256>>>(ff2W,  pwh + WH_FF2,  2048, 512);
    conv_half<<<(ROWS * INF_ / 2 + 255) / 256, 256>>>(feats, pfh, ROWS * INF_ / 2);

    // x = feats @ projW + projB + posenc (f32 px + half pxh)
    gemm_h<2><<<dim3(4, 64), 256, GH_SMEM>>>(pfh, pwh + WH_PROJ, projB, posenc,
                                             px, pxh, 512, 64);

    for (int l = 0; l < LL; l++) {
        gemm_h<0><<<dim3(12, 64), 256, GH_SMEM>>>(pxh, pwh + WH_QKV + (size_t)l * 393216,
                                                  qkvB + l * 3 * DD, nullptr,
                                                  pqkv, nullptr, 1536, 512);
        attn_mma<<<BB * HH * 16, 256, ATTN_SMEM>>>(pqkv, pctxh);
        gemm_h<0><<<dim3(4, 64), 256, GH_SMEM>>>(pctxh, pwh + WH_OUT + (size_t)l * 131072,
                                                 outB + l * DD, nullptr,
                                                 ptmp, nullptr, 512, 512);
        add_ln<1><<<ROWS, 128>>>(px, ptmp, ln1s + l * DD, ln1b + l * DD, px, pxh);
        gemm_h<1><<<dim3(16, 64), 256, GH_SMEM>>>(pxh, pwh + WH_FF1 + (size_t)l * 524288,
                                                  ff1B + l * FF_, nullptr,
                                                  nullptr, pffh, 2048, 512);
        gemm_h<0><<<dim3(4, 64), 256, GH_SMEM>>>(pffh, pwh + WH_FF2 + (size_t)l * 524288,
                                                 ff2B + l * DD, nullptr,
                                                 ptmp, nullptr, 512, 2048);
        if (l == LL - 1)
            add_ln<0><<<ROWS, 128>>>(px, ptmp, ln2s + l * DD, ln2b + l * DD, emb, nullptr);
        else
            add_ln<1><<<ROWS, 128>>>(px, ptmp, ln2s + l * DD, ln2b + l * DD, px, pxh);
    }

    pool_partial<<<BB * 32, DD>>>(emb, ppp);
    pool_reduce<<<BB, DD>>>(ppp, ppool);
    small_linear<<<BB, 2 * LAT>>>(ppool, mu1W, mu1B, ph, DD, 2 * LAT, 1);
    small_linear<<<BB, LAT>>>(ph, mu2W, mu2B, mu, 2 * LAT, LAT, 0);
    small_linear<<<BB, 2 * LAT>>>(ppool, lv1W, lv1B, ph, DD, 2 * LAT, 1);
    small_linear<<<BB, LAT>>>(ph, lv2W, lv2B, lv, 2 * LAT, LAT, 0);
}

// round 12
// speedup vs baseline: 3.1696x; 1.1592x over previous
#include <cuda_runtime.h>
#include <cuda_fp16.h>
#include <math.h>
#include <stdint.h>

// Problem constants
#define BB 4
#define TT 2048
#define INF_ 64
#define DD 512
#define HH 8
#define DH 64
#define FF_ 2048
#define LL 4
#define LAT 128
#define PAST 40
#define FUT 120
#define ROWS (BB*TT)          // 8192
#define EPS 1e-5f

// ---------------- scratch (device globals; no allocation allowed) ----------
__device__ float   g_x   [ROWS * DD];
__device__ float   g_tmp [ROWS * DD];
__device__ float   g_pool[BB * DD];
__device__ float   g_pp  [BB * 32 * DD];
__device__ float   g_h   [BB * 2 * LAT];
__device__ __half  g_xh  [ROWS * DD];        // half mirror of x (GEMM A)
__device__ __half  g_qkvh[ROWS * 3 * DD];    // qkv (half)
__device__ __half  g_ctxh[ROWS * DD];        // attention output (half)
__device__ __half  g_ffh [ROWS * FF_];       // ff1 output (half)
__device__ __half  g_fh  [ROWS * INF_];      // feats (half)
__device__ uint32_t g_wh [6307840];          // weights k-pair-packed half2

// word offsets into g_wh
#define WH_PROJ 0
#define WH_QKV  16384
#define WH_OUT  1589248
#define WH_FF1  2113536
#define WH_FF2  4210688

// ---------------- helpers ---------------------------------------------------
__device__ __forceinline__ uint32_t pack_h2f(float lo, float hi) {
    __half2 h = __floats2half2_rn(lo, hi);
    return *reinterpret_cast<uint32_t*>(&h);
}
__device__ __forceinline__ uint32_t sptr(const void* p) {
    return (uint32_t)__cvta_generic_to_shared(p);
}
__device__ __forceinline__ void cpa16(uint32_t dst, const void* src) {
    asm volatile("cp.async.cg.shared.global [%0], [%1], 16;\n" :: "r"(dst), "l"(src));
}
#define CP_COMMIT() asm volatile("cp.async.commit_group;\n")
#define CP_WAIT(n)  asm volatile("cp.async.wait_group %0;\n" :: "n"(n))

#define MMA_F16(d0,d1,d2,d3,a0,a1,a2,a3,b0,b1)                               \
    asm volatile("mma.sync.aligned.m16n8k16.row.col.f32.f16.f16.f32 "        \
        "{%0,%1,%2,%3},{%4,%5,%6,%7},{%8,%9},{%0,%1,%2,%3};"                 \
        : "+f"(d0),"+f"(d1),"+f"(d2),"+f"(d3)                                \
        : "r"(a0),"r"(a1),"r"(a2),"r"(a3),"r"(b0),"r"(b1))

#define LDMATRIX_X4(r0,r1,r2,r3,addr)                                        \
    asm volatile("ldmatrix.sync.aligned.m8n8.x4.shared.b16 {%0,%1,%2,%3}, [%4];" \
        : "=r"(r0),"=r"(r1),"=r"(r2),"=r"(r3) : "r"(addr))

// ---------------- weight pack: Wp[kp][n] = {h(W[2kp][n]), h(W[2kp+1][n])} ---
__global__ void pack_w(const float* __restrict__ W, uint32_t* __restrict__ Wp,
                       int K, int N)
{
    const int wpl = (K >> 1) * N;
    const float* Wz = W + (size_t)blockIdx.z * K * N;
    uint32_t* Wpz = Wp + (size_t)blockIdx.z * wpl;
    const int w = blockIdx.x * 256 + threadIdx.x;
    if (w >= wpl) return;
    const int kp = w / N, n = w - kp * N;
    Wpz[w] = pack_h2f(Wz[(size_t)(2 * kp) * N + n], Wz[(size_t)(2 * kp + 1) * N + n]);
}

// ---------------- f32 -> half convert ---------------------------------------
__global__ void conv_half(const float* __restrict__ in, __half* __restrict__ out,
                          int n2)
{
    const int i = blockIdx.x * 256 + threadIdx.x;
    if (i >= n2) return;
    const float2 v = ((const float2*)in)[i];
    ((__half2*)out)[i] = __floats2half2_rn(v.x, v.y);
}

// ---------------- FP16 GEMM, cp.async 3-stage, ldmatrix A-frags -------------
// C[M,N] = A[M,K] @ B[K,N] + bias. BM=BN=128, BK=32, 8 warps.
// EPI: 0 = +bias -> C f32 ; 1 = +bias, relu -> Ch half ;
//      2 = +bias+posenc -> C f32 AND Ch half ; 3 = +bias -> Ch half
#define AP2 20
#define BP2 136
#define GH_ASZ (128 * AP2)
#define GH_BSZ (16 * BP2)
#define GH_SMEM (3 * (GH_ASZ + GH_BSZ) * 4)   // 56832 B

template <int EPI>
__global__ __launch_bounds__(256, 2)
void gemm_h(const __half* __restrict__ A, const uint32_t* __restrict__ Bp,
            const float* __restrict__ bias, const float* __restrict__ extra,
            float* __restrict__ C, __half* __restrict__ Ch, int N, int K)
{
    extern __shared__ uint32_t smw[];
    uint32_t* As = smw;
    uint32_t* Bs = smw + 3 * GH_ASZ;

    const int tid  = threadIdx.x;
    const int wid  = tid >> 5, lane = tid & 31;
    const int g    = lane >> 2, c = lane & 3;
    const int wm   = (wid >> 2) * 64;
    const int wn   = (wid & 3) * 32;
    const int brow = blockIdx.y * 128, bcol = blockIdx.x * 128;

    const int arow = tid >> 1, ach = tid & 1;
    const int bkr = tid >> 4, bn0 = (tid & 15) * 8;

    const __half* Ag = A + (size_t)(brow + arow) * K + ach * 16;
    const uint32_t* Bg = Bp + bcol + bn0 + (size_t)bkr * N;

    const uint32_t sA = sptr(As) + (uint32_t)(arow * AP2 + ach * 8) * 4u;
    const uint32_t sB = sptr(Bs) + (uint32_t)(bkr * BP2 + bn0) * 4u;
    // ldmatrix lane offset: row = lane&15, col-16B = lane>>4
    const uint32_t lmoff = (uint32_t)((lane & 15) * AP2 + (lane >> 4) * 4) * 4u;

    float acc[4][4][4];
#pragma unroll
    for (int i = 0; i < 4; i++)
#pragma unroll
        for (int j = 0; j < 4; j++)
#pragma unroll
            for (int r = 0; r < 4; r++) acc[i][j][r] = 0.f;

    const int nk = K >> 5;

    {
        cpa16(sA, Ag);  cpa16(sA + 16, Ag + 8);
        cpa16(sB, Bg);  cpa16(sB + 16, Bg + 4);
        CP_COMMIT();
        if (nk > 1) {
            cpa16(sA + GH_ASZ * 4, Ag + 32);
            cpa16(sA + GH_ASZ * 4 + 16, Ag + 40);
            cpa16(sB + GH_BSZ * 4, Bg + (size_t)16 * N);
            cpa16(sB + GH_BSZ * 4 + 16, Bg + (size_t)16 * N + 4);
            CP_COMMIT();
            CP_WAIT(1);
        } else {
            CP_WAIT(0);
        }
        __syncthreads();
    }

    int s_cur = 0;
    for (int s = 0; s < nk; s++) {
        if (s + 2 < nk) {
            const int sl = (s_cur + 2 >= 3) ? s_cur - 1 : s_cur + 2;
            const __half* ga = Ag + (size_t)(s + 2) * 32;
            cpa16(sA + sl * GH_ASZ * 4, ga);
            cpa16(sA + sl * GH_ASZ * 4 + 16, ga + 8);
            const uint32_t* gb = Bg + (size_t)(s + 2) * 16 * N;
            cpa16(sB + sl * GH_BSZ * 4, gb);
            cpa16(sB + sl * GH_BSZ * 4 + 16, gb + 4);
            CP_COMMIT();
        }

        const uint32_t aBase = sptr(As) + (uint32_t)(s_cur * GH_ASZ) * 4u + lmoff;
        const uint32_t* Bb = Bs + s_cur * GH_BSZ;
#pragma unroll
        for (int kk = 0; kk < 2; kk++) {
            uint32_t af[4][4];
#pragma unroll
            for (int mt = 0; mt < 4; mt++) {
                const uint32_t addr = aBase
                    + (uint32_t)(((wm + mt * 16) * AP2 + kk * 8) * 4);
                LDMATRIX_X4(af[mt][0], af[mt][1], af[mt][2], af[mt][3], addr);
            }
            uint32_t bf[4][2];
#pragma unroll
            for (int nt = 0; nt < 4; nt++) {
                const int n0 = wn + nt * 8 + g;
                bf[nt][0] = Bb[(kk * 8 + c    ) * BP2 + n0];
                bf[nt][1] = Bb[(kk * 8 + c + 4) * BP2 + n0];
            }
#pragma unroll
            for (int mt = 0; mt < 4; mt++)
#pragma unroll
                for (int nt = 0; nt < 4; nt++)
                    MMA_F16(acc[mt][nt][0], acc[mt][nt][1], acc[mt][nt][2], acc[mt][nt][3],
                            af[mt][0], af[mt][1], af[mt][2], af[mt][3],
                            bf[nt][0], bf[nt][1]);
        }

        if (s + 1 < nk) {
            if (s + 2 < nk) CP_WAIT(1); else CP_WAIT(0);
            __syncthreads();
        }
        s_cur = (s_cur + 1 >= 3) ? 0 : s_cur + 1;
    }

    // epilogue
#pragma unroll
    for (int mt = 0; mt < 4; mt++) {
#pragma unroll
        for (int nt = 0; nt < 4; nt++) {
            const int col = bcol + wn + nt * 8 + 2 * c;
            const float b0 = bias[col], b1 = bias[col + 1];
#pragma unroll
            for (int half = 0; half < 2; half++) {
                const int row = brow + wm + mt * 16 + g + half * 8;
                float v0 = acc[mt][nt][half * 2 + 0] + b0;
                float v1 = acc[mt][nt][half * 2 + 1] + b1;
                if (EPI == 1) {
                    v0 = fmaxf(v0, 0.f); v1 = fmaxf(v1, 0.f);
                    *(__half2*)(Ch + (size_t)row * N + col) = __floats2half2_rn(v0, v1);
                } else if (EPI == 3) {
                    *(__half2*)(Ch + (size_t)row * N + col) = __floats2half2_rn(v0, v1);
                } else {
                    if (EPI == 2) {
                        const int t = row & (TT - 1);
                        v0 += extra[(size_t)t * N + col];
                        v1 += extra[(size_t)t * N + col + 1];
                        *(__half2*)(Ch + (size_t)row * N + col) = __floats2half2_rn(v0, v1);
                    }
                    float2 o; o.x = v0; o.y = v1;
                    *(float2*)(C + (size_t)row * N + col) = o;
                }
            }
        }
    }
}

// ---------------- banded flash attention, full fp16 --------------------------
// Block: 128 queries of one (b,h). 8 warps, 16 rows each. Chunks of 64 keys.
// Q@K^T: fp16 m16n8k16, B-words = raw adjacent half pairs from K rows.
// P@V:   fp16 m16n8k16, A-words packed directly from softmax registers.
#define KVPH 72                      // halves per K/V row (64 + 8 pad)
#define ABUFH (64 * KVPH)            // halves per buffer
#define ATTN_SMEM (4 * ABUFH * 2)    // 36864 B

__global__ __launch_bounds__(256, 2)
void attn_h(const __half* __restrict__ qkvh, __half* __restrict__ ctxh)
{
    extern __shared__ __half smh[];
    __half* Ks = smh;                // [2][64][72]
    __half* Vs = smh + 2 * ABUFH;

    const int blk = blockIdx.x;
    const int qt = blk & 15;
    const int h  = (blk >> 4) & 7;
    const int b  = blk >> 7;
    const int q0 = qt * 128;

    const int tid = threadIdx.x, wid = tid >> 5, lane = tid & 31;
    const int g = lane >> 2, c = lane & 3;
    const int w0 = q0 + wid * 16;
    const int r0 = w0 + g, r1 = r0 + 8;

    // ---- Q fragments: 4 k-steps of 16 dh each
    uint32_t qa[4][4];
    {
        const uint32_t* qlo = (const uint32_t*)(qkvh + (size_t)(b * TT + r0) * 1536 + h * 64);
        const uint32_t* qhi = (const uint32_t*)(qkvh + (size_t)(b * TT + r1) * 1536 + h * 64);
#pragma unroll
        for (int kt = 0; kt < 4; kt++) {
            qa[kt][0] = qlo[kt * 8 + c];
            qa[kt][1] = qhi[kt * 8 + c];
            qa[kt][2] = qlo[kt * 8 + c + 4];
            qa[kt][3] = qhi[kt * 8 + c + 4];
        }
    }

    float oacc[8][4];
#pragma unroll
    for (int nt = 0; nt < 8; nt++)
#pragma unroll
        for (int e = 0; e < 4; e++) oacc[nt][e] = 0.f;

    float m0 = -INFINITY, m1 = -INFINITY, l0 = 0.f, l1 = 0.f;
    const float scale = 0.125f;

    int csv[5]; int ncs = 0;
    const int offs[5] = {-64, 0, 64, 128, 192};
#pragma unroll
    for (int i = 0; i < 5; i++) {
        const int cs = q0 + offs[i];
        if (cs >= 0 && cs < TT) csv[ncs++] = cs;
    }

    // loader: 256 threads; row = (tid>>1)&63, K/V sel = tid>>7, half-row = tid&1
    const int lrow  = (tid >> 1) & 63;
    const int isv   = tid >> 7;
    const int lhalf = tid & 1;
    const uint32_t ldst0 = sptr((isv ? Vs : Ks) + lrow * KVPH + lhalf * 32);
    const size_t lsrc_off = (size_t)512 + (size_t)isv * 512 + h * 64 + lhalf * 32;

    {
        const __half* src = qkvh + (size_t)(b * TT + csv[0] + lrow) * 1536 + lsrc_off;
#pragma unroll
        for (int i = 0; i < 4; i++) cpa16(ldst0 + i * 16, src + i * 8);
        CP_COMMIT();
    }

    for (int ci = 0; ci < ncs; ci++) {
        CP_WAIT(0);
        __syncthreads();

        if (ci + 1 < ncs) {
            const uint32_t dst = ldst0 + ((ci + 1) & 1) * ABUFH * 2;
            const __half* src = qkvh + (size_t)(b * TT + csv[ci + 1] + lrow) * 1536 + lsrc_off;
#pragma unroll
            for (int i = 0; i < 4; i++) cpa16(dst + i * 16, src + i * 8);
            CP_COMMIT();
        }

        const int cs = csv[ci];
        const int lo_key = max(cs, w0 - PAST);
        const int hi_key = min(cs + 63, w0 + 15 + FUT);
        if (lo_key > hi_key) continue;
        const int ntlo = (lo_key - cs) >> 3;
        const int nthi = (hi_key - cs) >> 3;

        const __half* Kb = Ks + (ci & 1) * ABUFH;
        const __half* Vb = Vs + (ci & 1) * ABUFH;

        // ---- S = Q @ K^T (fp16)
        float sacc[8][4];
#pragma unroll
        for (int nt = 0; nt < 8; nt++) {
            sacc[nt][0] = 0.f; sacc[nt][1] = 0.f;
            sacc[nt][2] = 0.f; sacc[nt][3] = 0.f;
        }
#pragma unroll
        for (int nt = 0; nt < 8; nt++) {
            if (nt < ntlo || nt > nthi) continue;
            const __half* krow = Kb + (nt * 8 + g) * KVPH;
#pragma unroll
            for (int kt = 0; kt < 4; kt++) {
                const uint32_t b0 = *(const uint32_t*)(krow + kt * 16 + 2 * c);
                const uint32_t b1 = *(const uint32_t*)(krow + kt * 16 + 2 * c + 8);
                MMA_F16(sacc[nt][0], sacc[nt][1], sacc[nt][2], sacc[nt][3],
                        qa[kt][0], qa[kt][1], qa[kt][2], qa[kt][3], b0, b1);
            }
        }

        // ---- mask + row max
        float mx0 = -INFINITY, mx1 = -INFINITY;
#pragma unroll
        for (int nt = 0; nt < 8; nt++) {
            if (nt < ntlo || nt > nthi) continue;
            const int j0 = cs + nt * 8 + 2 * c;
            const int j1 = j0 + 1;
            float v;
            v = sacc[nt][0] * scale;
            v = (j0 >= r0 - PAST && j0 <= r0 + FUT) ? v : -INFINITY;
            sacc[nt][0] = v; mx0 = fmaxf(mx0, v);
            v = sacc[nt][1] * scale;
            v = (j1 >= r0 - PAST && j1 <= r0 + FUT) ? v : -INFINITY;
            sacc[nt][1] = v; mx0 = fmaxf(mx0, v);
            v = sacc[nt][2] * scale;
            v = (j0 >= r1 - PAST && j0 <= r1 + FUT) ? v : -INFINITY;
            sacc[nt][2] = v; mx1 = fmaxf(mx1, v);
            v = sacc[nt][3] * scale;
            v = (j1 >= r1 - PAST && j1 <= r1 + FUT) ? v : -INFINITY;
            sacc[nt][3] = v; mx1 = fmaxf(mx1, v);
        }
        mx0 = fmaxf(mx0, __shfl_xor_sync(0xffffffffu, mx0, 1));
        mx0 = fmaxf(mx0, __shfl_xor_sync(0xffffffffu, mx0, 2));
        mx1 = fmaxf(mx1, __shfl_xor_sync(0xffffffffu, mx1, 1));
        mx1 = fmaxf(mx1, __shfl_xor_sync(0xffffffffu, mx1, 2));

        const float mn0 = fmaxf(m0, mx0);
        const float mn1 = fmaxf(m1, mx1);
        const float rf0 = __expf(fmaxf(m0 - mn0, -88.f));
        const float rf1 = __expf(fmaxf(m1 - mn1, -88.f));
        m0 = mn0; m1 = mn1;

        // ---- p = exp(s - m) in place, row sums (invalid nt stay 0)
        float ps0 = 0.f, ps1 = 0.f;
#pragma unroll
        for (int nt = 0; nt < 8; nt++) {
            if (nt < ntlo || nt > nthi) continue;
            const float p00 = __expf(fmaxf(sacc[nt][0] - mn0, -88.f));
            const float p01 = __expf(fmaxf(sacc[nt][1] - mn0, -88.f));
            const float p10 = __expf(fmaxf(sacc[nt][2] - mn1, -88.f));
            const float p11 = __expf(fmaxf(sacc[nt][3] - mn1, -88.f));
            ps0 += p00 + p01;
            ps1 += p10 + p11;
            sacc[nt][0] = p00; sacc[nt][1] = p01;
            sacc[nt][2] = p10; sacc[nt][3] = p11;
        }
        ps0 += __shfl_xor_sync(0xffffffffu, ps0, 1);
        ps0 += __shfl_xor_sync(0xffffffffu, ps0, 2);
        ps1 += __shfl_xor_sync(0xffffffffu, ps1, 1);
        ps1 += __shfl_xor_sync(0xffffffffu, ps1, 2);
        l0 = l0 * rf0 + ps0;
        l1 = l1 * rf1 + ps1;

#pragma unroll
        for (int nt = 0; nt < 8; nt++) {
            oacc[nt][0] *= rf0; oacc[nt][1] *= rf0;
            oacc[nt][2] *= rf1; oacc[nt][3] *= rf1;
        }

        // ---- O += P @ V (fp16): A packed from sacc, B from 2x u16 loads
#pragma unroll
        for (int kp = 0; kp < 4; kp++) {
            const int nt0 = 2 * kp, nt1 = 2 * kp + 1;
            if (nt1 < ntlo || nt0 > nthi) continue;
            const uint32_t a0 = pack_h2f(sacc[nt0][0], sacc[nt0][1]);
            const uint32_t a1 = pack_h2f(sacc[nt0][2], sacc[nt0][3]);
            const uint32_t a2 = pack_h2f(sacc[nt1][0], sacc[nt1][1]);
            const uint32_t a3 = pack_h2f(sacc[nt1][2], sacc[nt1][3]);
            const __half* v0r = Vb + (kp * 16 + 2 * c) * KVPH;      // key 2c
            const __half* v1r = v0r + KVPH;                          // key 2c+1
            const __half* v8r = v0r + 8 * KVPH;                      // key 2c+8
            const __half* v9r = v8r + KVPH;                          // key 2c+9
#pragma unroll
            for (int nt = 0; nt < 8; nt++) {
                const int n = nt * 8 + g;
                const uint32_t b0 = *reinterpret_cast<const uint32_t*>(
                    &__halves2half2(v0r[n], v1r[n]));
                const uint32_t b1 = *reinterpret_cast<const uint32_t*>(
                    &__halves2half2(v8r[n], v9r[n]));
                MMA_F16(oacc[nt][0], oacc[nt][1], oacc[nt][2], oacc[nt][3],
                        a0, a1, a2, a3, b0, b1);
            }
        }
    }

    // ---- write O (half)
    const float inv0 = 1.f / l0, inv1 = 1.f / l1;
#pragma unroll
    for (int nt = 0; nt < 8; nt++) {
        const int col = h * 64 + nt * 8 + 2 * c;
        *(__half2*)(ctxh + (size_t)(b * TT + r0) * DD + col) =
            __floats2half2_rn(oacc[nt][0] * inv0, oacc[nt][1] * inv0);
        *(__half2*)(ctxh + (size_t)(b * TT + r1) * DD + col) =
            __floats2half2_rn(oacc[nt][2] * inv1, oacc[nt][3] * inv1);
    }
}

// ---------------- residual add + LayerNorm (optional half mirror) -----------
template <int WRH>
__global__ __launch_bounds__(128)
void add_ln(const float* __restrict__ x, const float* __restrict__ y,
            const float* __restrict__ s, const float* __restrict__ bta,
            float* __restrict__ out, __half* __restrict__ outh)
{
    const int row = blockIdx.x;
    const int tid = threadIdx.x;
    float v[4];
    float sum = 0.f, sq = 0.f;
#pragma unroll
    for (int i = 0; i < 4; i++) {
        int c = tid + i * 128;
        float val = x[(size_t)row * DD + c] + y[(size_t)row * DD + c];
        v[i] = val;
        sum += val;
        sq  += val * val;
    }
    __shared__ float rs[8];
#pragma unroll
    for (int off = 16; off > 0; off >>= 1) {
        sum += __shfl_xor_sync(0xffffffffu, sum, off);
        sq  += __shfl_xor_sync(0xffffffffu, sq,  off);
    }
    if ((tid & 31) == 0) { rs[tid >> 5] = sum; rs[4 + (tid >> 5)] = sq; }
    __syncthreads();
    sum = rs[0] + rs[1] + rs[2] + rs[3];
    sq  = rs[4] + rs[5] + rs[6] + rs[7];
    const float mean = sum * (1.f / DD);
    const float var  = sq * (1.f / DD) - mean * mean;
    const float inv  = rsqrtf(var + EPS);
#pragma unroll
    for (int i = 0; i < 4; i++) {
        int c = tid + i * 128;
        const float o = (v[i] - mean) * inv * s[c] + bta[c];
        out[(size_t)row * DD + c] = o;
        if (WRH) outh[(size_t)row * DD + c] = __float2half_rn(o);
    }
}

// ---------------- mean pool (two-stage) -------------------------------------
__global__ void pool_partial(const float* __restrict__ emb, float* __restrict__ pp)
{
    const int b = blockIdx.x >> 5, ch = blockIdx.x & 31;
    const int d = threadIdx.x;
    float s = 0.f;
    const int t0 = ch * 64;
    for (int t = t0; t < t0 + 64; t++)
        s += emb[((size_t)(b * TT + t)) * DD + d];
    pp[(size_t)blockIdx.x * DD + d] = s;
}

__global__ void pool_reduce(const float* __restrict__ pp, float* __restrict__ p)
{
    const int b = blockIdx.x, d = threadIdx.x;
    float s = 0.f;
    for (int ch = 0; ch < 32; ch++)
        s += pp[(size_t)(b * 32 + ch) * DD + d];
    p[b * DD + d] = s * (1.f / TT);
}

// ---------------- tiny dense layer (heads) ----------------------------------
__global__ void small_linear(const float* __restrict__ in, const float* __restrict__ W,
                             const float* __restrict__ bias, float* __restrict__ out,
                             int K, int N, int relu)
{
    const int b = blockIdx.x, n = threadIdx.x;
    if (n >= N) return;
    float sum = bias[n];
    for (int k = 0; k < K; k++)
        sum = fmaf(in[b * K + k], W[(size_t)k * N + n], sum);
    if (relu) sum = fmaxf(sum, 0.f);
    out[b * N + n] = sum;
}

// ---------------- launch -----------------------------------------------------
extern "C" void kernel_launch(void* const* d_in, const int* in_sizes, int n_in,
                              void* d_out, int out_size)
{
    const float* feats  = (const float*)d_in[0];
    const float* projW  = (const float*)d_in[1];
    const float* projB  = (const float*)d_in[2];
    const float* posenc = (const float*)d_in[3];
    const float* qkvW   = (const float*)d_in[4];
    const float* qkvB   = (const float*)d_in[5];
    const float* outW   = (const float*)d_in[6];
    const float* outB   = (const float*)d_in[7];
    const float* ln1s   = (const float*)d_in[8];
    const float* ln1b   = (const float*)d_in[9];
    const float* ff1W   = (const float*)d_in[10];
    const float* ff1B   = (const float*)d_in[11];
    const float* ff2W   = (const float*)d_in[12];
    const float* ff2B   = (const float*)d_in[13];
    const float* ln2s   = (const float*)d_in[14];
    const float* ln2b   = (const float*)d_in[15];
    const float* mu1W   = (const float*)d_in[16];
    const float* mu1B   = (const float*)d_in[17];
    const float* mu2W   = (const float*)d_in[18];
    const float* mu2B   = (const float*)d_in[19];
    const float* lv1W   = (const float*)d_in[20];
    const float* lv1B   = (const float*)d_in[21];
    const float* lv2W   = (const float*)d_in[22];
    const float* lv2B   = (const float*)d_in[23];

    float *px, *ptmp, *ppool, *ppp, *ph;
    __half *pxh, *pqkvh, *pctxh, *pffh, *pfh;
    uint32_t* pwh;
    cudaGetSymbolAddress((void**)&px,    g_x);
    cudaGetSymbolAddress((void**)&ptmp,  g_tmp);
    cudaGetSymbolAddress((void**)&ppool, g_pool);
    cudaGetSymbolAddress((void**)&ppp,   g_pp);
    cudaGetSymbolAddress((void**)&ph,    g_h);
    cudaGetSymbolAddress((void**)&pxh,   g_xh);
    cudaGetSymbolAddress((void**)&pqkvh, g_qkvh);
    cudaGetSymbolAddress((void**)&pctxh, g_ctxh);
    cudaGetSymbolAddress((void**)&pffh,  g_ffh);
    cudaGetSymbolAddress((void**)&pfh,   g_fh);
    cudaGetSymbolAddress((void**)&pwh,   g_wh);

    cudaFuncSetAttribute(gemm_h<0>, cudaFuncAttributeMaxDynamicSharedMemorySize, GH_SMEM);
    cudaFuncSetAttribute(gemm_h<1>, cudaFuncAttributeMaxDynamicSharedMemorySize, GH_SMEM);
    cudaFuncSetAttribute(gemm_h<2>, cudaFuncAttributeMaxDynamicSharedMemorySize, GH_SMEM);
    cudaFuncSetAttribute(gemm_h<3>, cudaFuncAttributeMaxDynamicSharedMemorySize, GH_SMEM);
    cudaFuncSetAttribute(attn_h,    cudaFuncAttributeMaxDynamicSharedMemorySize, ATTN_SMEM);

    float* emb = (float*)d_out;
    float* mu  = emb + (size_t)ROWS * DD;
    float* lv  = mu + BB * LAT;

    // pre-pack weights + convert feats
    pack_w<<<dim3(64, 1, 1),    256>>>(projW, pwh + WH_PROJ, 64, 512);
    pack_w<<<dim3(1536, 1, 4),  256>>>(qkvW,  pwh + WH_QKV,  512, 1536);
    pack_w<<<dim3(512, 1, 4),   256>>>(outW,  pwh + WH_OUT,  512, 512);
    pack_w<<<dim3(2048, 1, 4),  256>>>(ff1W,  pwh + WH_FF1,  512, 2048);
    pack_w<<<dim3(2048, 1, 4),  256>>>(ff2W,  pwh + WH_FF2,  2048, 512);
    conv_half<<<(ROWS * INF_ / 2 + 255) / 256, 256>>>(feats, pfh, ROWS * INF_ / 2);

    // x = feats @ projW + projB + posenc (f32 px + half pxh)
    gemm_h<2><<<dim3(4, 64), 256, GH_SMEM>>>(pfh, pwh + WH_PROJ, projB, posenc,
                                             px, pxh, 512, 64);

    for (int l = 0; l < LL; l++) {
        gemm_h<3><<<dim3(12, 64), 256, GH_SMEM>>>(pxh, pwh + WH_QKV + (size_t)l * 393216,
                                                  qkvB + l * 3 * DD, nullptr,
                                                  nullptr, pqkvh, 1536, 512);
        attn_h<<<BB * HH * 16, 256, ATTN_SMEM>>>(pqkvh, pctxh);
        gemm_h<0><<<dim3(4, 64), 256, GH_SMEM>>>(pctxh, pwh + WH_OUT + (size_t)l * 131072,
                                                 outB + l * DD, nullptr,
                                                 ptmp, nullptr, 512, 512);
        add_ln<1><<<ROWS, 128>>>(px, ptmp, ln1s + l * DD, ln1b + l * DD, px, pxh);
        gemm_h<1><<<dim3(16, 64), 256, GH_SMEM>>>(pxh, pwh + WH_FF1 + (size_t)l * 524288,
                                                  ff1B + l * FF_, nullptr,
                                                  nullptr, pffh, 2048, 512);
        gemm_h<0><<<dim3(4, 64), 256, GH_SMEM>>>(pffh, pwh + WH_FF2 + (size_t)l * 524288,
                                                 ff2B + l * DD, nullptr,
                                                 ptmp, nullptr, 512, 2048);
        if (l == LL - 1)
            add_ln<0><<<ROWS, 128>>>(px, ptmp, ln2s + l * DD, ln2b + l * DD, emb, nullptr);
        else
            add_ln<1><<<ROWS, 128>>>(px, ptmp, ln2s + l * DD, ln2b + l * DD, px, pxh);
    }

    pool_partial<<<BB * 32, DD>>>(emb, ppp);
    pool_reduce<<<BB, DD>>>(ppp, ppool);
    small_linear<<<BB, 2 * LAT>>>(ppool, mu1W, mu1B, ph, DD, 2 * LAT, 1);
    small_linear<<<BB, LAT>>>(ph, mu2W, mu2B, mu, 2 * LAT, LAT, 0);
    small_linear<<<BB, 2 * LAT>>>(ppool, lv1W, lv1B, ph, DD, 2 * LAT, 1);
    small_linear<<<BB, LAT>>>(ph, lv2W, lv2B, lv, 2 * LAT, LAT, 0);
}